// round 12
// baseline (speedup 1.0000x reference)
#include <cuda_runtime.h>
#include <cuda_bf16.h>
#include <stdint.h>
#include <math.h>

#define NPTS 8192
#define NBLOCKS 148
#define NTHREADS 512
#define TILES 512

#define MU 80.77f
#define LAM 121.15f
#define GC 2.7e-3f
#define LEN 0.015f

// ---- SMEM byte offsets ----
#define SM_AHI   0        // A hi: 128 rows x 256B (bf16, swizzled)
#define SM_ALO   32768
#define SM_W1HI  65536    // W k-major [k][n] bf16, swizzled
#define SM_W1LO  98304
#define SM_W2HI  131072
#define SM_W2LO  163840
#define SM_W0P   196608   // float4[128]: (W0r0, W0r1, W0r2, b0)
#define SM_W3P   198656   // float4[128]: (W3[j][0..2], 0)
#define SM_B1    200704
#define SM_B2    201216
#define SM_PARTJ 201728   // float[16 pts][2 cg][8 ch][4]
#define SMEM_TOTAL 205824

__device__ double g_part[NBLOCKS][3];
__device__ int g_count = 0;

__device__ __forceinline__ uint32_t smem_u32_of(const void* p) {
    uint32_t a;
    asm("{ .reg .u64 tmp; cvta.to.shared.u64 tmp, %1; cvt.u32.u64 %0, tmp; }"
        : "=r"(a) : "l"(p));
    return a;
}
__device__ __forceinline__ void ldsm4(uint32_t r[4], uint32_t addr) {
    asm volatile("ldmatrix.sync.aligned.m8n8.x4.shared.b16 {%0,%1,%2,%3}, [%4];"
                 : "=r"(r[0]), "=r"(r[1]), "=r"(r[2]), "=r"(r[3]) : "r"(addr));
}
__device__ __forceinline__ void ldsm4t(uint32_t r[4], uint32_t addr) {
    asm volatile("ldmatrix.sync.aligned.m8n8.x4.trans.shared.b16 {%0,%1,%2,%3}, [%4];"
                 : "=r"(r[0]), "=r"(r[1]), "=r"(r[2]), "=r"(r[3]) : "r"(addr));
}
__device__ __forceinline__ void mma16816(float c[4], const uint32_t a[4],
                                         uint32_t b0, uint32_t b1) {
    asm volatile(
        "mma.sync.aligned.m16n8k16.row.col.f32.bf16.bf16.f32 "
        "{%0,%1,%2,%3}, {%4,%5,%6,%7}, {%8,%9}, {%0,%1,%2,%3};"
        : "+f"(c[0]), "+f"(c[1]), "+f"(c[2]), "+f"(c[3])
        : "r"(a[0]), "r"(a[1]), "r"(a[2]), "r"(a[3]), "r"(b0), "r"(b1));
}

// write one activation value into A hi/lo (bf16 split, swizzled) - seed path
__device__ __forceinline__ void writeA_pair(char* smem, int row, int jj, float v) {
    uint32_t off = (uint32_t)row * 256u
                 + ((((uint32_t)(jj >> 3) ^ ((uint32_t)row & 15u)) << 4)
                 | (((uint32_t)jj & 7u) << 1));
    __nv_bfloat16 h = __float2bfloat16(v);
    *(__nv_bfloat16*)(smem + SM_AHI + off) = h;
    *(__nv_bfloat16*)(smem + SM_ALO + off) = __float2bfloat16(v - __bfloat162float(h));
}

// 128x128x128 bf16 3-term split GEMM; acc = per-warp C fragments
__device__ __forceinline__ void gemm_layer(uint32_t su, int rb, int cg, int lane,
                                           uint32_t whi_off, float acc[4][2][4]) {
#pragma unroll
    for (int nb = 0; nb < 4; nb++)
#pragma unroll
        for (int h = 0; h < 2; h++)
#pragma unroll
            for (int e = 0; e < 4; e++) acc[nb][h][e] = 0.f;

    const int m = lane >> 3;
    const int row_a = rb * 16 + (lane & 7) + ((m & 1) << 3);
    const int krow_l = (lane & 7) + ((m & 1) << 3);
#pragma unroll
    for (int k = 0; k < 8; k++) {
        uint32_t ua = (uint32_t)((k * 2 + (m >> 1)) ^ (row_a & 15));
        uint32_t aaddr = su + SM_AHI + (uint32_t)row_a * 256u + ua * 16u;
        uint32_t ahi[4], alo[4];
        ldsm4(ahi, aaddr);
        ldsm4(alo, aaddr + 32768u);
#pragma unroll
        for (int nb = 0; nb < 4; nb++) {
            int ncol = cg * 64 + nb * 16;
            int krow = k * 16 + krow_l;
            uint32_t un = (uint32_t)((((ncol >> 3) + (m >> 1))) ^ (krow & 15));
            uint32_t baddr = su + whi_off + (uint32_t)krow * 256u + un * 16u;
            uint32_t bhi[4], blo[4];
            ldsm4t(bhi, baddr);
            ldsm4t(blo, baddr + 32768u);
#pragma unroll
            for (int h = 0; h < 2; h++) {
                mma16816(acc[nb][h], ahi, bhi[2 * h], bhi[2 * h + 1]);
                mma16816(acc[nb][h], ahi, blo[2 * h], blo[2 * h + 1]);
                mma16816(acc[nb][h], alo, bhi[2 * h], bhi[2 * h + 1]);
            }
        }
    }
}

// Intra-warp shfl epilogue. Fragment map (validated in R11):
//  acc[nb][h][e]: row = rb*16 + (e>=2 ? 8 : 0) + g ; col = cg*64+nb*16+h*8+2*tg+(e&1)
//  lane channel = g (0..7); point A = 2rb (e<2), point B = 2rb+1 (e>=2).
// LAYER==1: writes next A (bf16 hi/lo). LAYER==2: folds W3 into Jp[point][3].
template <int LAYER>
__device__ __forceinline__ void epilogue(char* smem, int rb, int cg, int lane,
                                         float acc[4][2][4], float Jp[2][3])
{
    const int g = lane >> 2, tg = lane & 3;

    // gather z0 (channel-0 rows live in g==0 lanes) to duty lanes
    float z0d[4];
#pragma unroll
    for (int nb = 0; nb < 4; nb++)
#pragma unroll
        for (int h = 0; h < 2; h++) {
            const int gd = nb * 2 + h;
#pragma unroll
            for (int j = 0; j < 4; j++) {
                float v = __shfl_sync(0xffffffffu, acc[nb][h][j], tg);
                if (g == gd) z0d[j] = v;
            }
        }
    // duty lane (g,tg) owns (nb,h) = (g>>1, g&1); computes T for its 4 (e,p)
    const float* B = (const float*)(smem + (LAYER == 1 ? SM_B1 : SM_B2));
    float Td[4];
#pragma unroll
    for (int j = 0; j < 4; j++) {
        int col = cg * 64 + (g >> 1) * 16 + (g & 1) * 8 + 2 * tg + (j & 1);
        Td[j] = tanhf(z0d[j] + B[col]);
    }

    if (LAYER == 1) {
        // partner warp (same rb, other cg) must finish reading A before we overwrite
        asm volatile("bar.sync %0, 64;" :: "r"(1 + rb) : "memory");
    }

    const float4* W3P = (const float4*)(smem + SM_W3P);
#pragma unroll
    for (int nb = 0; nb < 4; nb++)
#pragma unroll
        for (int h = 0; h < 2; h++) {
            const int srcd = ((nb * 2 + h) << 2) | tg;
            const int colp = cg * 64 + nb * 16 + h * 8 + 2 * tg;
#pragma unroll
            for (int p = 0; p < 2; p++) {
                float ov[2];
#pragma unroll
                for (int e = 0; e < 2; e++) {
                    const int j = e + 2 * p;
                    float T  = __shfl_sync(0xffffffffu, Td[j], srcd);
                    float z1 = __shfl_sync(0xffffffffu, acc[nb][h][j], 4 + tg);
                    float z2 = __shfl_sync(0xffffffffu, acc[nb][h][j], 8 + tg);
                    float zo = acc[nb][h][j];
                    float Sx = 1.f - T * T;
                    float o;
                    if (g == 0) o = T;
                    else if (g < 4) o = Sx * zo;
                    else if (g == 7) o = 0.f;
                    else {
                        float c2 = -2.f * T * Sx;
                        float qq = (g == 4) ? z1 * z1 : (g == 5 ? z1 * z2 : z2 * z2);
                        o = fmaf(c2, qq, Sx * zo);
                    }
                    ov[e] = o;
                }
                if (LAYER == 1) {
                    int row = rb * 16 + 8 * p + g;
                    uint32_t off = (uint32_t)row * 256u
                        + ((uint32_t)(((colp >> 3) ^ row) & 15) << 4)
                        + (uint32_t)(4 * tg);
                    uint32_t hi, lo;
                    asm("cvt.rn.satfinite.bf16x2.f32 %0, %1, %2;"
                        : "=r"(hi) : "f"(ov[1]), "f"(ov[0]));
                    float l0 = ov[0] - __uint_as_float(hi << 16);
                    float l1 = ov[1] - __uint_as_float(hi & 0xffff0000u);
                    asm("cvt.rn.satfinite.bf16x2.f32 %0, %1, %2;"
                        : "=r"(lo) : "f"(l1), "f"(l0));
                    *(uint32_t*)(smem + SM_AHI + off) = hi;
                    *(uint32_t*)(smem + SM_ALO + off) = lo;
                } else {
                    float4 wa = W3P[colp];
                    float4 wb = W3P[colp + 1];
                    Jp[p][0] = fmaf(ov[0], wa.x, fmaf(ov[1], wb.x, Jp[p][0]));
                    Jp[p][1] = fmaf(ov[0], wa.y, fmaf(ov[1], wb.y, Jp[p][1]));
                    Jp[p][2] = fmaf(ov[0], wa.z, fmaf(ov[1], wb.z, Jp[p][2]));
                }
            }
        }
}

__global__ __launch_bounds__(NTHREADS, 1)
void pinn_kernel(const float* __restrict__ x,  const float* __restrict__ t,
                 const float* __restrict__ W0, const float* __restrict__ b0,
                 const float* __restrict__ W1, const float* __restrict__ b1,
                 const float* __restrict__ W2, const float* __restrict__ b2,
                 const float* __restrict__ W3, const float* __restrict__ b3,
                 float* __restrict__ out)
{
    extern __shared__ char smem[];
    const uint32_t su = smem_u32_of(smem);
    const int tid = threadIdx.x, warp = tid >> 5, lane = tid & 31;
    const int rb = warp & 7, cg = warp >> 3;
    const int g = lane >> 2, tg = lane & 3;

    // ---- init: weights (k-major, bf16 hi/lo, swizzled), vectors ----
    for (int idx = tid; idx < 16384; idx += NTHREADS) {
        int k = idx >> 7, n = idx & 127;
        uint32_t off = (uint32_t)k * 256u
                     + ((((uint32_t)(n >> 3) ^ ((uint32_t)k & 15u)) << 4)
                     | (((uint32_t)n & 7u) << 1));
        float w = W1[idx];
        __nv_bfloat16 h = __float2bfloat16(w);
        *(__nv_bfloat16*)(smem + SM_W1HI + off) = h;
        *(__nv_bfloat16*)(smem + SM_W1LO + off) = __float2bfloat16(w - __bfloat162float(h));
        w = W2[idx];
        h = __float2bfloat16(w);
        *(__nv_bfloat16*)(smem + SM_W2HI + off) = h;
        *(__nv_bfloat16*)(smem + SM_W2LO + off) = __float2bfloat16(w - __bfloat162float(h));
    }
    for (int j = tid; j < 128; j += NTHREADS) {
        ((float4*)(smem + SM_W0P))[j] = make_float4(W0[j], W0[128 + j], W0[256 + j], b0[j]);
        ((float4*)(smem + SM_W3P))[j] = make_float4(W3[3 * j], W3[3 * j + 1], W3[3 * j + 2], 0.f);
        ((float*)(smem + SM_B1))[j] = b1[j];
        ((float*)(smem + SM_B2))[j] = b2[j];
    }
    __syncthreads();

    const int t0 = (blockIdx.x * TILES) / NBLOCKS;
    const int t1 = ((blockIdx.x + 1) * TILES) / NBLOCKS;
    double a0 = 0.0, a1 = 0.0, a2 = 0.0;
    const float b3v = b3[0];
    float acc[4][2][4];

    for (int tile = t0; tile < t1; tile++) {
        // ---- layer-0 analytic jet seed -> A ----
#pragma unroll
        for (int it = 0; it < 4; it++) {
            int jj = tid & 127;
            int p = (tid >> 7) + it * 4;
            int gp = tile * 16 + p;
            float x1 = x[2 * gp], x2 = x[2 * gp + 1], ttv = t[gp];
            float4 w = ((const float4*)(smem + SM_W0P))[jj];
            float z = fmaf(ttv, w.z, fmaf(x2, w.y, fmaf(x1, w.x, w.w)));
            float T = tanhf(z);
            float Sx = 1.f - T * T;
            float c2 = -2.f * T * Sx;
            float o[8] = {T, Sx * w.x, Sx * w.y, Sx * w.z,
                          c2 * w.x * w.x, c2 * w.x * w.y, c2 * w.y * w.y, 0.f};
#pragma unroll
            for (int c = 0; c < 8; c++) writeA_pair(smem, p * 8 + c, jj, o[c]);
        }
        __syncthreads();

        // ---- hidden layer 1: GEMM + shfl epilogue (writes next A) ----
        gemm_layer(su, rb, cg, lane, SM_W1HI, acc);
        epilogue<1>(smem, rb, cg, lane, acc, (float(*)[3])0);
        // A writes of both cg-warps complete before layer-2 GEMM reads
        asm volatile("bar.sync %0, 64;" :: "r"(1 + rb) : "memory");

        // ---- hidden layer 2: GEMM + shfl epilogue (folds W3) ----
        gemm_layer(su, rb, cg, lane, SM_W2HI, acc);
        float Jp[2][3] = {{0.f, 0.f, 0.f}, {0.f, 0.f, 0.f}};
        epilogue<2>(smem, rb, cg, lane, acc, Jp);

        // reduce partial J across tg (lanes share channel g), write PARTJ
#pragma unroll
        for (int p = 0; p < 2; p++)
#pragma unroll
            for (int k = 0; k < 3; k++) {
                Jp[p][k] += __shfl_xor_sync(0xffffffffu, Jp[p][k], 1);
                Jp[p][k] += __shfl_xor_sync(0xffffffffu, Jp[p][k], 2);
            }
        if (tg == 0) {
            float* PJ = (float*)(smem + SM_PARTJ);
#pragma unroll
            for (int p = 0; p < 2; p++) {
                int pt = 2 * rb + p;
#pragma unroll
                for (int k = 0; k < 3; k++)
                    PJ[((pt * 2 + cg) * 8 + g) * 4 + k] = Jp[p][k];
            }
        }
        __syncthreads();

        // ---- physics residuals (warp 0, one lane per point) ----
        if (warp == 0 && lane < 16) {
            const float* PJ = (const float*)(smem + SM_PARTJ);
            float J0[7], J1[7], J2[7];
#pragma unroll
            for (int c = 0; c < 7; c++) {
                int b0i = ((lane * 2 + 0) * 8 + c) * 4;
                int b1i = ((lane * 2 + 1) * 8 + c) * 4;
                J0[c] = PJ[b0i + 0] + PJ[b1i + 0];
                J1[c] = PJ[b0i + 1] + PJ[b1i + 1];
                J2[c] = PJ[b0i + 2] + PJ[b1i + 2];
            }
            float s0v = J0[0] + b3v;
            float phi = expf(-s0v);
            float div1 = (MU + LAM) * (J1[4] + J2[5]) + MU * (J1[4] + J1[6]);
            float div2 = (MU + LAM) * (J1[5] + J2[6]) + MU * (J2[4] + J2[6]);
            float om = 1.f - phi, gq = om * om;
            float res_stress = fabsf(gq * div1) + fabsf(gq * div2);
            float tr = J1[1] + J2[2];
            float trp = 0.5f * (tr + fabsf(tr));
            float pos = 0.5f * (LAM + MU) * trp * trp;
            float e12 = 0.5f * (J1[2] + J2[1]);
            float d11 = J1[1] - 0.5f * tr;
            float d22 = J2[2] - 0.5f * tr;
            float psi = pos + MU * (d11 * d11 + d22 * d22 + 2.f * e12 * e12);
            float lap = phi * (J0[1] * J0[1] + J0[2] * J0[2] - J0[4] - J0[6]);
            float pf = GC * (phi / LEN - LEN * lap) - 2.f * om * psi;
            float irr = fmaxf(phi * J0[3], 0.f);
            a0 += (double)(res_stress * res_stress);
            a1 += (double)(pf * pf);
            a2 += (double)irr;
        }
        // next iteration's seed writes A (disjoint from PARTJ); the __syncthreads
        // after seed orders physics reads before the next PARTJ writes
    }

    if (warp == 0) {
#pragma unroll
        for (int off = 8; off; off >>= 1) {
            a0 += __shfl_down_sync(0xffffffffu, a0, off);
            a1 += __shfl_down_sync(0xffffffffu, a1, off);
            a2 += __shfl_down_sync(0xffffffffu, a2, off);
        }
        if (lane == 0) {
            g_part[blockIdx.x][0] = a0;
            g_part[blockIdx.x][1] = a1;
            g_part[blockIdx.x][2] = a2;
        }
    }

    __shared__ int is_last;
    __syncthreads();
    if (tid == 0) {
        __threadfence();
        is_last = (atomicAdd(&g_count, 1) == NBLOCKS - 1) ? 1 : 0;
    }
    __syncthreads();
    if (is_last && warp == 0) {
        __threadfence();
        double s0 = 0.0, s1 = 0.0, s2 = 0.0;
        for (int i = lane; i < NBLOCKS; i += 32) {
            s0 += g_part[i][0]; s1 += g_part[i][1]; s2 += g_part[i][2];
        }
#pragma unroll
        for (int off = 16; off; off >>= 1) {
            s0 += __shfl_down_sync(0xffffffffu, s0, off);
            s1 += __shfl_down_sync(0xffffffffu, s1, off);
            s2 += __shfl_down_sync(0xffffffffu, s2, off);
        }
        if (lane == 0) {
            out[0] = (float)(s0 / (double)NPTS);
            out[1] = (float)(s1 / (double)NPTS);
            out[2] = (float)(s2 / (double)NPTS);
            g_count = 0;
        }
    }
}

extern "C" void kernel_launch(void* const* d_in, const int* in_sizes, int n_in,
                              void* d_out, int out_size)
{
    const float* x  = (const float*)d_in[0];
    const float* t  = (const float*)d_in[1];
    const float* W0 = (const float*)d_in[2];
    const float* b0 = (const float*)d_in[3];
    const float* W1 = (const float*)d_in[4];
    const float* b1 = (const float*)d_in[5];
    const float* W2 = (const float*)d_in[6];
    const float* b2 = (const float*)d_in[7];
    const float* W3 = (const float*)d_in[8];
    const float* b3 = (const float*)d_in[9];

    cudaFuncSetAttribute(pinn_kernel,
                         cudaFuncAttributeMaxDynamicSharedMemorySize, SMEM_TOTAL);
    pinn_kernel<<<NBLOCKS, NTHREADS, SMEM_TOTAL>>>(
        x, t, W0, b0, W1, b1, W2, b2, W3, b3, (float*)d_out);
}

// round 13
// speedup vs baseline: 1.5632x; 1.5632x over previous
#include <cuda_runtime.h>
#include <cuda_bf16.h>
#include <stdint.h>
#include <math.h>

#define NPTS 8192
#define NBLOCKS 148
#define NTHREADS 512
#define TILES 512

#define MU 80.77f
#define LAM 121.15f
#define GC 2.7e-3f
#define LEN 0.015f

// ---- SMEM byte offsets ----
#define SM_AHI   0        // A hi: 128 rows x 256B (bf16, swizzled); half h owns rows h*64..
#define SM_ALO   32768
#define SM_W1HI  65536    // W k-major [k][n] bf16, swizzled
#define SM_W1LO  98304
#define SM_W2HI  131072
#define SM_W2LO  163840
#define SM_STAGE 196608   // per-half C stage: 32 cols x 68 floats = 8704 B, x2
#define SM_W0P   214016   // float4[128]: (W0r0, W0r1, W0r2, b0)
#define SM_W3P   216064   // float4[128]: (W3[j][0..2], 0)
#define SM_B1    218112
#define SM_B2    218624
#define SM_PARTJ 219136   // float[16 pts][24]
#define SM_WRED  220672   // double[16][3]
#define SMEM_TOTAL 221184

#define STAGE_H 8704

__device__ double g_part[NBLOCKS][3];
__device__ int g_count = 0;

__device__ __forceinline__ uint32_t smem_u32_of(const void* p) {
    uint32_t a;
    asm("{ .reg .u64 tmp; cvta.to.shared.u64 tmp, %1; cvt.u32.u64 %0, tmp; }"
        : "=r"(a) : "l"(p));
    return a;
}
__device__ __forceinline__ void barh(int half) {
    asm volatile("bar.sync %0, 256;" :: "r"(half + 1) : "memory");
}
__device__ __forceinline__ void ldsm4(uint32_t r[4], uint32_t addr) {
    asm volatile("ldmatrix.sync.aligned.m8n8.x4.shared.b16 {%0,%1,%2,%3}, [%4];"
                 : "=r"(r[0]), "=r"(r[1]), "=r"(r[2]), "=r"(r[3]) : "r"(addr));
}
__device__ __forceinline__ void ldsm4t(uint32_t r[4], uint32_t addr) {
    asm volatile("ldmatrix.sync.aligned.m8n8.x4.trans.shared.b16 {%0,%1,%2,%3}, [%4];"
                 : "=r"(r[0]), "=r"(r[1]), "=r"(r[2]), "=r"(r[3]) : "r"(addr));
}
__device__ __forceinline__ void mma16816(float c[4], const uint32_t a[4],
                                         uint32_t b0, uint32_t b1) {
    asm volatile(
        "mma.sync.aligned.m16n8k16.row.col.f32.bf16.bf16.f32 "
        "{%0,%1,%2,%3}, {%4,%5,%6,%7}, {%8,%9}, {%0,%1,%2,%3};"
        : "+f"(c[0]), "+f"(c[1]), "+f"(c[2]), "+f"(c[3])
        : "r"(a[0]), "r"(a[1]), "r"(a[2]), "r"(a[3]), "r"(b0), "r"(b1));
}

// write one activation value into A hi/lo (bf16 split, swizzled)
__device__ __forceinline__ void writeA_pair(char* smem, int row, int jj, float v) {
    uint32_t off = (uint32_t)row * 256u
                 + ((((uint32_t)(jj >> 3) ^ ((uint32_t)row & 15u)) << 4)
                 | (((uint32_t)jj & 7u) << 1));
    __nv_bfloat16 h = __float2bfloat16(v);
    *(__nv_bfloat16*)(smem + SM_AHI + off) = h;
    *(__nv_bfloat16*)(smem + SM_ALO + off) = __float2bfloat16(v - __bfloat162float(h));
}

// per-half 64x128x128 bf16 3-term split GEMM (warp: 16 rows x 64 cols)
__device__ __forceinline__ void gemm_layer(uint32_t su, int ro, int rb, int cg,
                                           int lane, uint32_t whi_off,
                                           float acc[4][2][4]) {
#pragma unroll
    for (int nb = 0; nb < 4; nb++)
#pragma unroll
        for (int h = 0; h < 2; h++)
#pragma unroll
            for (int e = 0; e < 4; e++) acc[nb][h][e] = 0.f;

    const int m = lane >> 3;
    const int row_a = ro + rb * 16 + (lane & 7) + ((m & 1) << 3);
    const int krow_l = (lane & 7) + ((m & 1) << 3);
#pragma unroll
    for (int k = 0; k < 8; k++) {
        uint32_t ua = (uint32_t)((k * 2 + (m >> 1)) ^ (row_a & 15));
        uint32_t aaddr = su + SM_AHI + (uint32_t)row_a * 256u + ua * 16u;
        uint32_t ahi[4], alo[4];
        ldsm4(ahi, aaddr);
        ldsm4(alo, aaddr + 32768u);
#pragma unroll
        for (int nb = 0; nb < 4; nb++) {
            int ncol = cg * 64 + nb * 16;
            int krow = k * 16 + krow_l;
            uint32_t un = (uint32_t)((((ncol >> 3) + (m >> 1))) ^ (krow & 15));
            uint32_t baddr = su + whi_off + (uint32_t)krow * 256u + un * 16u;
            uint32_t bhi[4], blo[4];
            ldsm4t(bhi, baddr);
            ldsm4t(blo, baddr + 32768u);
#pragma unroll
            for (int h = 0; h < 2; h++) {
                mma16816(acc[nb][h], ahi, bhi[2 * h], bhi[2 * h + 1]);
                mma16816(acc[nb][h], ahi, blo[2 * h], blo[2 * h + 1]);
                mma16816(acc[nb][h], alo, bhi[2 * h], bhi[2 * h + 1]);
            }
        }
    }
}

// stage this warp's fragments for 32-col chunk ch into the half's stage buffer
__device__ __forceinline__ void stage_chunk(char* smem, int half, int ch, int rb,
                                            int cg, int lane, float acc[4][2][4]) {
    if (cg != (ch >> 1)) return;
    float* st = (float*)(smem + SM_STAGE + half * STAGE_H);
    const int g = lane >> 2, tg = lane & 3;
#pragma unroll
    for (int tl = 0; tl < 2; tl++) {
        int tt = 2 * (ch & 1) + tl;
#pragma unroll
        for (int h = 0; h < 2; h++) {
            int jc = tl * 16 + h * 8 + 2 * tg;
            int base = jc * 68 + rb * 16 + g;
            st[base]          = acc[tt][h][0];
            st[base + 68]     = acc[tt][h][1];
            st[base + 8]      = acc[tt][h][2];
            st[base + 68 + 8] = acc[tt][h][3];
        }
    }
}

// activation epilogue for chunk ch; LAYER=1 writes next A, LAYER=2 folds W3
template <int LAYER>
__device__ __forceinline__ void epi_chunk(char* smem, int half, int ch,
                                          int tid_h, float* Jacc) {
    const int l = tid_h & 31, p = tid_h >> 5;      // col-in-chunk, point 0..7
    const int jj = ch * 32 + l;
    const float* st = (const float*)(smem + SM_STAGE + half * STAGE_H);
    float zs[8];
    *(float4*)zs       = *(const float4*)(st + l * 68 + p * 8);
    *(float4*)(zs + 4) = *(const float4*)(st + l * 68 + p * 8 + 4);
    const float bjj = ((const float*)(smem + (LAYER == 1 ? SM_B1 : SM_B2)))[jj];
    float z = zs[0] + bjj;
    float T = tanhf(z);
    float Sx = 1.f - T * T;
    float c2 = -2.f * T * Sx;
    float o[8];
    o[0] = T; o[1] = Sx * zs[1]; o[2] = Sx * zs[2]; o[3] = Sx * zs[3];
    o[4] = fmaf(c2 * zs[1], zs[1], Sx * zs[4]);
    o[5] = fmaf(c2 * zs[1], zs[2], Sx * zs[5]);
    o[6] = fmaf(c2 * zs[2], zs[2], Sx * zs[6]);
    o[7] = 0.f;
    if (LAYER == 1) {
#pragma unroll
        for (int c = 0; c < 8; c++)
            writeA_pair(smem, half * 64 + p * 8 + c, jj, o[c]);
    } else {
        float4 w3 = ((const float4*)(smem + SM_W3P))[jj];
#pragma unroll
        for (int c = 0; c < 7; c++) {
            Jacc[c * 3 + 0] = fmaf(o[c], w3.x, Jacc[c * 3 + 0]);
            Jacc[c * 3 + 1] = fmaf(o[c], w3.y, Jacc[c * 3 + 1]);
            Jacc[c * 3 + 2] = fmaf(o[c], w3.z, Jacc[c * 3 + 2]);
        }
    }
}

__global__ __launch_bounds__(NTHREADS, 1)
void pinn_kernel(const float* __restrict__ x,  const float* __restrict__ t,
                 const float* __restrict__ W0, const float* __restrict__ b0,
                 const float* __restrict__ W1, const float* __restrict__ b1,
                 const float* __restrict__ W2, const float* __restrict__ b2,
                 const float* __restrict__ W3, const float* __restrict__ b3,
                 float* __restrict__ out)
{
    extern __shared__ char smem[];
    const uint32_t su = smem_u32_of(smem);
    const int tid = threadIdx.x, warp = tid >> 5, lane = tid & 31;
    const int half = warp >> 3, wid8 = warp & 7;
    const int rb = wid8 & 3, cg = wid8 >> 2;
    const int ro = half * 64;
    const int tid_h = tid & 255;

    // ---- init: weights (k-major, bf16 hi/lo, swizzled), vectors ----
    for (int idx = tid; idx < 16384; idx += NTHREADS) {
        int k = idx >> 7, n = idx & 127;
        uint32_t off = (uint32_t)k * 256u
                     + ((((uint32_t)(n >> 3) ^ ((uint32_t)k & 15u)) << 4)
                     | (((uint32_t)n & 7u) << 1));
        float w = W1[idx];
        __nv_bfloat16 h = __float2bfloat16(w);
        *(__nv_bfloat16*)(smem + SM_W1HI + off) = h;
        *(__nv_bfloat16*)(smem + SM_W1LO + off) = __float2bfloat16(w - __bfloat162float(h));
        w = W2[idx];
        h = __float2bfloat16(w);
        *(__nv_bfloat16*)(smem + SM_W2HI + off) = h;
        *(__nv_bfloat16*)(smem + SM_W2LO + off) = __float2bfloat16(w - __bfloat162float(h));
    }
    for (int j = tid; j < 128; j += NTHREADS) {
        ((float4*)(smem + SM_W0P))[j] = make_float4(W0[j], W0[128 + j], W0[256 + j], b0[j]);
        ((float4*)(smem + SM_W3P))[j] = make_float4(W3[3 * j], W3[3 * j + 1], W3[3 * j + 2], 0.f);
        ((float*)(smem + SM_B1))[j] = b1[j];
        ((float*)(smem + SM_B2))[j] = b2[j];
    }
    __syncthreads();

    const int t0 = (blockIdx.x * TILES) / NBLOCKS;
    const int t1 = ((blockIdx.x + 1) * TILES) / NBLOCKS;
    double a0 = 0.0, a1 = 0.0, a2 = 0.0;
    const float b3v = b3[0];
    float acc[4][2][4];

    for (int tile = t0; tile < t1; tile++) {
        // ---- layer-0 analytic jet seed -> A (half's 64 rows) ----
        {
            int jj = tid_h & 127;
            int prow = tid_h >> 7;
#pragma unroll
            for (int it = 0; it < 4; it++) {
                int p = prow + 2 * it;                 // 0..7 within half
                int gp = tile * 16 + half * 8 + p;
                float x1 = x[2 * gp], x2 = x[2 * gp + 1], ttv = t[gp];
                float4 w = ((const float4*)(smem + SM_W0P))[jj];
                float z = fmaf(ttv, w.z, fmaf(x2, w.y, fmaf(x1, w.x, w.w)));
                float T = tanhf(z);
                float Sx = 1.f - T * T;
                float c2 = -2.f * T * Sx;
                float o[8] = {T, Sx * w.x, Sx * w.y, Sx * w.z,
                              c2 * w.x * w.x, c2 * w.x * w.y, c2 * w.y * w.y, 0.f};
#pragma unroll
                for (int c = 0; c < 8; c++)
                    writeA_pair(smem, ro + p * 8 + c, jj, o[c]);
            }
        }
        barh(half);

        // ---- hidden layer 1: GEMM + staged epilogue (writes next A) ----
        gemm_layer(su, ro, rb, cg, lane, SM_W1HI, acc);
        for (int ch = 0; ch < 4; ch++) {
            stage_chunk(smem, half, ch, rb, cg, lane, acc);
            barh(half);
            epi_chunk<1>(smem, half, ch, tid_h, (float*)0);
            barh(half);
        }

        // ---- hidden layer 2: GEMM + staged epilogue (folds W3) ----
        gemm_layer(su, ro, rb, cg, lane, SM_W2HI, acc);
        float Jacc[21];
#pragma unroll
        for (int c = 0; c < 21; c++) Jacc[c] = 0.f;
        for (int ch = 0; ch < 4; ch++) {
            stage_chunk(smem, half, ch, rb, cg, lane, acc);
            barh(half);
            epi_chunk<2>(smem, half, ch, tid_h, Jacc);
            barh(half);
        }
        // warp-reduce J over the 32 cols (each epi warp = one point)
#pragma unroll
        for (int c = 0; c < 21; c++) {
#pragma unroll
            for (int off = 16; off; off >>= 1)
                Jacc[c] += __shfl_down_sync(0xffffffffu, Jacc[c], off);
        }
        if (lane == 0) {
            float* PJ = (float*)(smem + SM_PARTJ) + (half * 8 + wid8) * 24;
#pragma unroll
            for (int c = 0; c < 21; c++) PJ[c] = Jacc[c];
        }
        barh(half);

        // ---- physics residuals (half's warp 0, one lane per point) ----
        if (wid8 == 0 && lane < 8) {
            const float* PJ = (const float*)(smem + SM_PARTJ) + (half * 8 + lane) * 24;
            float J0[7], J1[7], J2[7];
#pragma unroll
            for (int c = 0; c < 7; c++) {
                J0[c] = PJ[c * 3 + 0]; J1[c] = PJ[c * 3 + 1]; J2[c] = PJ[c * 3 + 2];
            }
            float s0v = J0[0] + b3v;
            float phi = expf(-s0v);
            float div1 = (MU + LAM) * (J1[4] + J2[5]) + MU * (J1[4] + J1[6]);
            float div2 = (MU + LAM) * (J1[5] + J2[6]) + MU * (J2[4] + J2[6]);
            float om = 1.f - phi, gq = om * om;
            float res_stress = fabsf(gq * div1) + fabsf(gq * div2);
            float tr = J1[1] + J2[2];
            float trp = 0.5f * (tr + fabsf(tr));
            float pos = 0.5f * (LAM + MU) * trp * trp;
            float e12 = 0.5f * (J1[2] + J2[1]);
            float d11 = J1[1] - 0.5f * tr;
            float d22 = J2[2] - 0.5f * tr;
            float psi = pos + MU * (d11 * d11 + d22 * d22 + 2.f * e12 * e12);
            float lap = phi * (J0[1] * J0[1] + J0[2] * J0[2] - J0[4] - J0[6]);
            float pf = GC * (phi / LEN - LEN * lap) - 2.f * om * psi;
            float irr = fmaxf(phi * J0[3], 0.f);
            a0 += (double)(res_stress * res_stress);
            a1 += (double)(pf * pf);
            a2 += (double)irr;
        }
        // PJ not rewritten until after next tile's layer-2 (many barriers away)
    }

    // ---- block reduction (deterministic) ----
#pragma unroll
    for (int off = 4; off; off >>= 1) {
        a0 += __shfl_down_sync(0xffffffffu, a0, off);
        a1 += __shfl_down_sync(0xffffffffu, a1, off);
        a2 += __shfl_down_sync(0xffffffffu, a2, off);
    }
    {
        double* wred = (double*)(smem + SM_WRED);
        __syncthreads();
        if (lane == 0) {
            wred[warp * 3 + 0] = a0;
            wred[warp * 3 + 1] = a1;
            wred[warp * 3 + 2] = a2;
        }
        __syncthreads();
        if (tid == 0) {
            double s0 = 0.0, s1 = 0.0, s2 = 0.0;
#pragma unroll
            for (int w = 0; w < 16; w++) {
                s0 += wred[w * 3 + 0]; s1 += wred[w * 3 + 1]; s2 += wred[w * 3 + 2];
            }
            g_part[blockIdx.x][0] = s0;
            g_part[blockIdx.x][1] = s1;
            g_part[blockIdx.x][2] = s2;
        }
    }

    __shared__ int is_last;
    __syncthreads();
    if (tid == 0) {
        __threadfence();
        is_last = (atomicAdd(&g_count, 1) == NBLOCKS - 1) ? 1 : 0;
    }
    __syncthreads();
    if (is_last && warp == 0) {
        __threadfence();
        double s0 = 0.0, s1 = 0.0, s2 = 0.0;
        for (int i = lane; i < NBLOCKS; i += 32) {
            s0 += g_part[i][0]; s1 += g_part[i][1]; s2 += g_part[i][2];
        }
#pragma unroll
        for (int off = 16; off; off >>= 1) {
            s0 += __shfl_down_sync(0xffffffffu, s0, off);
            s1 += __shfl_down_sync(0xffffffffu, s1, off);
            s2 += __shfl_down_sync(0xffffffffu, s2, off);
        }
        if (lane == 0) {
            out[0] = (float)(s0 / (double)NPTS);
            out[1] = (float)(s1 / (double)NPTS);
            out[2] = (float)(s2 / (double)NPTS);
            g_count = 0;
        }
    }
}

extern "C" void kernel_launch(void* const* d_in, const int* in_sizes, int n_in,
                              void* d_out, int out_size)
{
    const float* x  = (const float*)d_in[0];
    const float* t  = (const float*)d_in[1];
    const float* W0 = (const float*)d_in[2];
    const float* b0 = (const float*)d_in[3];
    const float* W1 = (const float*)d_in[4];
    const float* b1 = (const float*)d_in[5];
    const float* W2 = (const float*)d_in[6];
    const float* b2 = (const float*)d_in[7];
    const float* W3 = (const float*)d_in[8];
    const float* b3 = (const float*)d_in[9];

    cudaFuncSetAttribute(pinn_kernel,
                         cudaFuncAttributeMaxDynamicSharedMemorySize, SMEM_TOTAL);
    pinn_kernel<<<NBLOCKS, NTHREADS, SMEM_TOTAL>>>(
        x, t, W0, b0, W1, b1, W2, b2, W3, b3, (float*)d_out);
}

// round 14
// speedup vs baseline: 1.5918x; 1.0183x over previous
#include <cuda_runtime.h>
#include <cuda_bf16.h>
#include <stdint.h>
#include <math.h>

#define NPTS 8192
#define NBLOCKS 148
#define NTHREADS 512
#define TILES 512

#define MU 80.77f
#define LAM 121.15f
#define GC 2.7e-3f
#define LEN 0.015f

// ---- SMEM byte offsets ----
#define SM_AHI   0        // A hi: 128 rows x 256B (bf16, swizzled); half h rows h*64..
#define SM_ALO   32768    // A lo
#define SM_W1HI  65536    // W k-major [k][n] bf16, swizzled
#define SM_W1LO  98304
#define SM_W2HI  131072
#define SM_W2LO  163840
#define SM_W0P   196608   // float4[128]: (W0r0, W0r1, W0r2, b0)
#define SM_W3P   198656   // float4[128]: (W3[j][0..2], 0)
#define SM_B1    200704
#define SM_B2    201216
#define SM_PARTJ 201728   // float[16 pts][24]
#define SM_WRED  203264   // double[16][3]
#define SMEM_TOTAL 203776

// Stage (z matrix) aliases the dead A region of the same half:
//   col<64 -> A-hi 16KB slab, col>=64 -> A-lo slab. Layout [col&63][slot'],
//   pitch 64 floats, slot' = (8*pt + ch) ^ ((col&7)<<2)  (bank-conflict free).

__device__ double g_part[NBLOCKS][3];
__device__ int g_count = 0;

__device__ __forceinline__ uint32_t smem_u32_of(const void* p) {
    uint32_t a;
    asm("{ .reg .u64 tmp; cvta.to.shared.u64 tmp, %1; cvt.u32.u64 %0, tmp; }"
        : "=r"(a) : "l"(p));
    return a;
}
__device__ __forceinline__ void barh(int half) {
    asm volatile("bar.sync %0, 256;" :: "r"(half + 1) : "memory");
}
__device__ __forceinline__ void ldsm4(uint32_t r[4], uint32_t addr) {
    asm volatile("ldmatrix.sync.aligned.m8n8.x4.shared.b16 {%0,%1,%2,%3}, [%4];"
                 : "=r"(r[0]), "=r"(r[1]), "=r"(r[2]), "=r"(r[3]) : "r"(addr));
}
__device__ __forceinline__ void ldsm4t(uint32_t r[4], uint32_t addr) {
    asm volatile("ldmatrix.sync.aligned.m8n8.x4.trans.shared.b16 {%0,%1,%2,%3}, [%4];"
                 : "=r"(r[0]), "=r"(r[1]), "=r"(r[2]), "=r"(r[3]) : "r"(addr));
}
__device__ __forceinline__ void mma16816(float c[4], const uint32_t a[4],
                                         uint32_t b0, uint32_t b1) {
    asm volatile(
        "mma.sync.aligned.m16n8k16.row.col.f32.bf16.bf16.f32 "
        "{%0,%1,%2,%3}, {%4,%5,%6,%7}, {%8,%9}, {%0,%1,%2,%3};"
        : "+f"(c[0]), "+f"(c[1]), "+f"(c[2]), "+f"(c[3])
        : "r"(a[0]), "r"(a[1]), "r"(a[2]), "r"(a[3]), "r"(b0), "r"(b1));
}

// write one activation value into A hi/lo (bf16 split, swizzled)
__device__ __forceinline__ void writeA_pair(char* smem, int row, int jj, float v) {
    uint32_t off = (uint32_t)row * 256u
                 + ((((uint32_t)(jj >> 3) ^ ((uint32_t)row & 15u)) << 4)
                 | (((uint32_t)jj & 7u) << 1));
    __nv_bfloat16 h = __float2bfloat16(v);
    *(__nv_bfloat16*)(smem + SM_AHI + off) = h;
    *(__nv_bfloat16*)(smem + SM_ALO + off) = __float2bfloat16(v - __bfloat162float(h));
}

// per-half 64x128x128 bf16 3-term split GEMM (warp: 16 rows x 64 cols)
__device__ __forceinline__ void gemm_layer(uint32_t su, int ro, int rb, int cg,
                                           int lane, uint32_t whi_off,
                                           float acc[4][2][4]) {
#pragma unroll
    for (int nb = 0; nb < 4; nb++)
#pragma unroll
        for (int h = 0; h < 2; h++)
#pragma unroll
            for (int e = 0; e < 4; e++) acc[nb][h][e] = 0.f;

    const int m = lane >> 3;
    const int row_a = ro + rb * 16 + (lane & 7) + ((m & 1) << 3);
    const int krow_l = (lane & 7) + ((m & 1) << 3);
#pragma unroll
    for (int k = 0; k < 8; k++) {
        uint32_t ua = (uint32_t)((k * 2 + (m >> 1)) ^ (row_a & 15));
        uint32_t aaddr = su + SM_AHI + (uint32_t)row_a * 256u + ua * 16u;
        uint32_t ahi[4], alo[4];
        ldsm4(ahi, aaddr);
        ldsm4(alo, aaddr + 32768u);
#pragma unroll
        for (int nb = 0; nb < 4; nb++) {
            int ncol = cg * 64 + nb * 16;
            int krow = k * 16 + krow_l;
            uint32_t un = (uint32_t)((((ncol >> 3) + (m >> 1))) ^ (krow & 15));
            uint32_t baddr = su + whi_off + (uint32_t)krow * 256u + un * 16u;
            uint32_t bhi[4], blo[4];
            ldsm4t(bhi, baddr);
            ldsm4t(blo, baddr + 32768u);
#pragma unroll
            for (int h = 0; h < 2; h++) {
                mma16816(acc[nb][h], ahi, bhi[2 * h], bhi[2 * h + 1]);
                mma16816(acc[nb][h], ahi, blo[2 * h], blo[2 * h + 1]);
                mma16816(acc[nb][h], alo, bhi[2 * h], bhi[2 * h + 1]);
            }
        }
    }
}

// stage all fragments into the dead A region (full 128 cols at once)
__device__ __forceinline__ void stage_frags(char* smem, int half, int rb, int cg,
                                            int lane, float acc[4][2][4]) {
    const int g = lane >> 2, tg = lane & 3;
    const int rbase = (cg ? SM_ALO : SM_AHI) + half * 16384;
#pragma unroll
    for (int nb = 0; nb < 4; nb++)
#pragma unroll
        for (int h = 0; h < 2; h++)
#pragma unroll
            for (int e = 0; e < 4; e++) {
                int pt = 2 * rb + (e >> 1);
                int col = cg * 64 + nb * 16 + h * 8 + 2 * tg + (e & 1);
                int slotp = (8 * pt + g) ^ ((col & 7) << 2);
                *(float*)(smem + rbase + (((col & 63) << 6) + slotp) * 4)
                    = acc[nb][h][e];
            }
}

// read staged z for this thread's point p, cols l+32q, q=0..3 -> zs[q][0..7]
__device__ __forceinline__ void read_stage(char* smem, int half, int th,
                                           float zs[4][8]) {
    const int p = th >> 5, l = th & 31;
#pragma unroll
    for (int q = 0; q < 4; q++) {
        int col = l + 32 * q;
        char* rbase = smem + ((col >= 64) ? SM_ALO : SM_AHI) + half * 16384
                    + (col & 63) * 256;
        int bi = (8 * p) ^ ((col & 6) << 2);
        int lo4 = (col & 1) << 2;
        float4 f0 = *(float4*)(rbase + (bi + lo4) * 4);        // ch 0..3
        float4 f1 = *(float4*)(rbase + (bi + (lo4 ^ 4)) * 4);  // ch 4..7
        zs[q][0] = f0.x; zs[q][1] = f0.y; zs[q][2] = f0.z; zs[q][3] = f0.w;
        zs[q][4] = f1.x; zs[q][5] = f1.y; zs[q][6] = f1.z; zs[q][7] = f1.w;
    }
}

__global__ __launch_bounds__(NTHREADS, 1)
void pinn_kernel(const float* __restrict__ x,  const float* __restrict__ t,
                 const float* __restrict__ W0, const float* __restrict__ b0,
                 const float* __restrict__ W1, const float* __restrict__ b1,
                 const float* __restrict__ W2, const float* __restrict__ b2,
                 const float* __restrict__ W3, const float* __restrict__ b3,
                 float* __restrict__ out)
{
    extern __shared__ char smem[];
    const uint32_t su = smem_u32_of(smem);
    const int tid = threadIdx.x, warp = tid >> 5, lane = tid & 31;
    const int half = warp >> 3, wid8 = warp & 7;
    const int rb = wid8 & 3, cg = wid8 >> 2;
    const int ro = half * 64;
    const int tid_h = tid & 255;
    const int p_epi = tid_h >> 5, l_epi = tid_h & 31;

    // ---- init: weights (k-major, bf16 hi/lo, swizzled), vectors ----
    for (int idx = tid; idx < 16384; idx += NTHREADS) {
        int k = idx >> 7, n = idx & 127;
        uint32_t off = (uint32_t)k * 256u
                     + ((((uint32_t)(n >> 3) ^ ((uint32_t)k & 15u)) << 4)
                     | (((uint32_t)n & 7u) << 1));
        float w = W1[idx];
        __nv_bfloat16 h = __float2bfloat16(w);
        *(__nv_bfloat16*)(smem + SM_W1HI + off) = h;
        *(__nv_bfloat16*)(smem + SM_W1LO + off) = __float2bfloat16(w - __bfloat162float(h));
        w = W2[idx];
        h = __float2bfloat16(w);
        *(__nv_bfloat16*)(smem + SM_W2HI + off) = h;
        *(__nv_bfloat16*)(smem + SM_W2LO + off) = __float2bfloat16(w - __bfloat162float(h));
    }
    for (int j = tid; j < 128; j += NTHREADS) {
        ((float4*)(smem + SM_W0P))[j] = make_float4(W0[j], W0[128 + j], W0[256 + j], b0[j]);
        ((float4*)(smem + SM_W3P))[j] = make_float4(W3[3 * j], W3[3 * j + 1], W3[3 * j + 2], 0.f);
        ((float*)(smem + SM_B1))[j] = b1[j];
        ((float*)(smem + SM_B2))[j] = b2[j];
    }
    __syncthreads();

    const int t0 = (blockIdx.x * TILES) / NBLOCKS;
    const int t1 = ((blockIdx.x + 1) * TILES) / NBLOCKS;
    double a0 = 0.0, a1 = 0.0, a2 = 0.0;
    const float b3v = b3[0];
    float acc[4][2][4];
    float zs[4][8];

    for (int tile = t0; tile < t1; tile++) {
        // ---- layer-0 analytic jet seed -> A (half's 64 rows; ch7 skipped) ----
        {
            int jj = tid_h & 127;
            int prow = tid_h >> 7;
#pragma unroll
            for (int it = 0; it < 4; it++) {
                int p = prow + 2 * it;
                int gp = tile * 16 + half * 8 + p;
                float x1 = x[2 * gp], x2 = x[2 * gp + 1], ttv = t[gp];
                float4 w = ((const float4*)(smem + SM_W0P))[jj];
                float z = fmaf(ttv, w.z, fmaf(x2, w.y, fmaf(x1, w.x, w.w)));
                float T = tanhf(z);
                float Sx = 1.f - T * T;
                float c2 = -2.f * T * Sx;
                float o[7] = {T, Sx * w.x, Sx * w.y, Sx * w.z,
                              c2 * w.x * w.x, c2 * w.x * w.y, c2 * w.y * w.y};
#pragma unroll
                for (int c = 0; c < 7; c++)
                    writeA_pair(smem, ro + p * 8 + c, jj, o[c]);
            }
        }
        barh(half);

        // ---- hidden layer 1 ----
        gemm_layer(su, ro, rb, cg, lane, SM_W1HI, acc);
        barh(half);                         // all warps done reading A
        stage_frags(smem, half, rb, cg, lane, acc);
        barh(half);                         // stage (in dead A) ready
        read_stage(smem, half, tid_h, zs);
        barh(half);                         // reads in regs; A region free
        {
            const float* B1p = (const float*)(smem + SM_B1);
#pragma unroll
            for (int q = 0; q < 4; q++) {
                int jj = l_epi + 32 * q;
                float z = zs[q][0] + B1p[jj];
                float T = tanhf(z);
                float Sx = 1.f - T * T;
                float c2 = -2.f * T * Sx;
                float o[7];
                o[0] = T; o[1] = Sx * zs[q][1]; o[2] = Sx * zs[q][2]; o[3] = Sx * zs[q][3];
                o[4] = fmaf(c2 * zs[q][1], zs[q][1], Sx * zs[q][4]);
                o[5] = fmaf(c2 * zs[q][1], zs[q][2], Sx * zs[q][5]);
                o[6] = fmaf(c2 * zs[q][2], zs[q][2], Sx * zs[q][6]);
#pragma unroll
                for (int c = 0; c < 7; c++)
                    writeA_pair(smem, ro + p_epi * 8 + c, jj, o[c]);
            }
        }
        barh(half);                         // new A ready

        // ---- hidden layer 2 ----
        gemm_layer(su, ro, rb, cg, lane, SM_W2HI, acc);
        barh(half);
        stage_frags(smem, half, rb, cg, lane, acc);
        barh(half);
        read_stage(smem, half, tid_h, zs);
        float Jacc[21];
#pragma unroll
        for (int c = 0; c < 21; c++) Jacc[c] = 0.f;
        {
            const float* B2p = (const float*)(smem + SM_B2);
            const float4* W3P = (const float4*)(smem + SM_W3P);
#pragma unroll
            for (int q = 0; q < 4; q++) {
                int jj = l_epi + 32 * q;
                float z = zs[q][0] + B2p[jj];
                float T = tanhf(z);
                float Sx = 1.f - T * T;
                float c2 = -2.f * T * Sx;
                float o[7];
                o[0] = T; o[1] = Sx * zs[q][1]; o[2] = Sx * zs[q][2]; o[3] = Sx * zs[q][3];
                o[4] = fmaf(c2 * zs[q][1], zs[q][1], Sx * zs[q][4]);
                o[5] = fmaf(c2 * zs[q][1], zs[q][2], Sx * zs[q][5]);
                o[6] = fmaf(c2 * zs[q][2], zs[q][2], Sx * zs[q][6]);
                float4 w3 = W3P[jj];
#pragma unroll
                for (int c = 0; c < 7; c++) {
                    Jacc[c * 3 + 0] = fmaf(o[c], w3.x, Jacc[c * 3 + 0]);
                    Jacc[c * 3 + 1] = fmaf(o[c], w3.y, Jacc[c * 3 + 1]);
                    Jacc[c * 3 + 2] = fmaf(o[c], w3.z, Jacc[c * 3 + 2]);
                }
            }
        }
        // warp-reduce J over 32 lanes (warp p_epi = one point)
#pragma unroll
        for (int c = 0; c < 21; c++) {
#pragma unroll
            for (int off = 16; off; off >>= 1)
                Jacc[c] += __shfl_down_sync(0xffffffffu, Jacc[c], off);
        }
        if (lane == 0) {
            float* PJ = (float*)(smem + SM_PARTJ) + (half * 8 + wid8) * 24;
#pragma unroll
            for (int c = 0; c < 21; c++) PJ[c] = Jacc[c];
        }
        barh(half);

        // ---- physics residuals (half's warp 0, one lane per point) ----
        if (wid8 == 0 && lane < 8) {
            const float* PJ = (const float*)(smem + SM_PARTJ) + (half * 8 + lane) * 24;
            float J0[7], J1[7], J2[7];
#pragma unroll
            for (int c = 0; c < 7; c++) {
                J0[c] = PJ[c * 3 + 0]; J1[c] = PJ[c * 3 + 1]; J2[c] = PJ[c * 3 + 2];
            }
            float s0v = J0[0] + b3v;
            float phi = expf(-s0v);
            float div1 = (MU + LAM) * (J1[4] + J2[5]) + MU * (J1[4] + J1[6]);
            float div2 = (MU + LAM) * (J1[5] + J2[6]) + MU * (J2[4] + J2[6]);
            float om = 1.f - phi, gq = om * om;
            float res_stress = fabsf(gq * div1) + fabsf(gq * div2);
            float tr = J1[1] + J2[2];
            float trp = 0.5f * (tr + fabsf(tr));
            float pos = 0.5f * (LAM + MU) * trp * trp;
            float e12 = 0.5f * (J1[2] + J2[1]);
            float d11 = J1[1] - 0.5f * tr;
            float d22 = J2[2] - 0.5f * tr;
            float psi = pos + MU * (d11 * d11 + d22 * d22 + 2.f * e12 * e12);
            float lap = phi * (J0[1] * J0[1] + J0[2] * J0[2] - J0[4] - J0[6]);
            float pf = GC * (phi / LEN - LEN * lap) - 2.f * om * psi;
            float irr = fmaxf(phi * J0[3], 0.f);
            a0 += (double)(res_stress * res_stress);
            a1 += (double)(pf * pf);
            a2 += (double)irr;
        }
    }

    // ---- block reduction (deterministic) ----
#pragma unroll
    for (int off = 4; off; off >>= 1) {
        a0 += __shfl_down_sync(0xffffffffu, a0, off);
        a1 += __shfl_down_sync(0xffffffffu, a1, off);
        a2 += __shfl_down_sync(0xffffffffu, a2, off);
    }
    {
        double* wred = (double*)(smem + SM_WRED);
        __syncthreads();
        if (lane == 0) {
            wred[warp * 3 + 0] = a0;
            wred[warp * 3 + 1] = a1;
            wred[warp * 3 + 2] = a2;
        }
        __syncthreads();
        if (tid == 0) {
            double s0 = 0.0, s1 = 0.0, s2 = 0.0;
#pragma unroll
            for (int w = 0; w < 16; w++) {
                s0 += wred[w * 3 + 0]; s1 += wred[w * 3 + 1]; s2 += wred[w * 3 + 2];
            }
            g_part[blockIdx.x][0] = s0;
            g_part[blockIdx.x][1] = s1;
            g_part[blockIdx.x][2] = s2;
        }
    }

    __shared__ int is_last;
    __syncthreads();
    if (tid == 0) {
        __threadfence();
        is_last = (atomicAdd(&g_count, 1) == NBLOCKS - 1) ? 1 : 0;
    }
    __syncthreads();
    if (is_last && warp == 0) {
        __threadfence();
        double s0 = 0.0, s1 = 0.0, s2 = 0.0;
        for (int i = lane; i < NBLOCKS; i += 32) {
            s0 += g_part[i][0]; s1 += g_part[i][1]; s2 += g_part[i][2];
        }
#pragma unroll
        for (int off = 16; off; off >>= 1) {
            s0 += __shfl_down_sync(0xffffffffu, s0, off);
            s1 += __shfl_down_sync(0xffffffffu, s1, off);
            s2 += __shfl_down_sync(0xffffffffu, s2, off);
        }
        if (lane == 0) {
            out[0] = (float)(s0 / (double)NPTS);
            out[1] = (float)(s1 / (double)NPTS);
            out[2] = (float)(s2 / (double)NPTS);
            g_count = 0;
        }
    }
}

extern "C" void kernel_launch(void* const* d_in, const int* in_sizes, int n_in,
                              void* d_out, int out_size)
{
    const float* x  = (const float*)d_in[0];
    const float* t  = (const float*)d_in[1];
    const float* W0 = (const float*)d_in[2];
    const float* b0 = (const float*)d_in[3];
    const float* W1 = (const float*)d_in[4];
    const float* b1 = (const float*)d_in[5];
    const float* W2 = (const float*)d_in[6];
    const float* b2 = (const float*)d_in[7];
    const float* W3 = (const float*)d_in[8];
    const float* b3 = (const float*)d_in[9];

    cudaFuncSetAttribute(pinn_kernel,
                         cudaFuncAttributeMaxDynamicSharedMemorySize, SMEM_TOTAL);
    pinn_kernel<<<NBLOCKS, NTHREADS, SMEM_TOTAL>>>(
        x, t, W0, b0, W1, b1, W2, b2, W3, b3, (float*)d_out);
}

// round 15
// speedup vs baseline: 1.6206x; 1.0181x over previous
#include <cuda_runtime.h>
#include <cuda_bf16.h>
#include <stdint.h>
#include <math.h>

#define NPTS 8192
#define NBLOCKS 148
#define NTHREADS 512
#define TILES 512

#define MU 80.77f
#define LAM 121.15f
#define GC 2.7e-3f
#define LEN 0.015f

// ---- SMEM byte offsets ----
#define SM_AHI   0        // A hi: 128 rows x 256B (bf16, swizzled); half h rows h*64..
#define SM_ALO   32768    // A lo
#define SM_W1HI  65536    // W k-major [k][n] bf16, swizzled
#define SM_W1LO  98304
#define SM_W2HI  131072
#define SM_W2LO  163840
#define SM_W0P   196608   // float4[128]: (W0r0, W0r1, W0r2, b0)
#define SM_W3P   198656   // float4[128]: (W3[j][0..2], 0)
#define SM_B1    200704
#define SM_B2    201216
#define SM_PARTJ 201728   // float[16 pts][24]
#define SM_WRED  203264   // double[16][3]
#define SMEM_TOTAL 203776

// Stage (z matrix) aliases the dead A region of the same half:
//   col<64 -> A-hi slab, col>=64 -> A-lo slab. [col&63][slot], pitch 64 floats,
//   slot = (8*pt + ch) ^ ((col&7)<<2) ^ (((col>>3)&1)<<2)  (conflict-free for
//   fragment stores AND even-column paired reads).

__device__ double g_part[NBLOCKS][3];
__device__ int g_count = 0;

__device__ __forceinline__ uint32_t smem_u32_of(const void* p) {
    uint32_t a;
    asm("{ .reg .u64 tmp; cvta.to.shared.u64 tmp, %1; cvt.u32.u64 %0, tmp; }"
        : "=r"(a) : "l"(p));
    return a;
}
__device__ __forceinline__ void barh(int half) {
    asm volatile("bar.sync %0, 256;" :: "r"(half + 1) : "memory");
}
__device__ __forceinline__ void ldsm4(uint32_t r[4], uint32_t addr) {
    asm volatile("ldmatrix.sync.aligned.m8n8.x4.shared.b16 {%0,%1,%2,%3}, [%4];"
                 : "=r"(r[0]), "=r"(r[1]), "=r"(r[2]), "=r"(r[3]) : "r"(addr));
}
__device__ __forceinline__ void ldsm4t(uint32_t r[4], uint32_t addr) {
    asm volatile("ldmatrix.sync.aligned.m8n8.x4.trans.shared.b16 {%0,%1,%2,%3}, [%4];"
                 : "=r"(r[0]), "=r"(r[1]), "=r"(r[2]), "=r"(r[3]) : "r"(addr));
}
__device__ __forceinline__ void mma16816(float c[4], const uint32_t a[4],
                                         uint32_t b0, uint32_t b1) {
    asm volatile(
        "mma.sync.aligned.m16n8k16.row.col.f32.bf16.bf16.f32 "
        "{%0,%1,%2,%3}, {%4,%5,%6,%7}, {%8,%9}, {%0,%1,%2,%3};"
        : "+f"(c[0]), "+f"(c[1]), "+f"(c[2]), "+f"(c[3])
        : "r"(a[0]), "r"(a[1]), "r"(a[2]), "r"(a[3]), "r"(b0), "r"(b1));
}

// fast tanh: abs error ~1e-7 (MUFU ex2 + approx div), far inside tolerance
__device__ __forceinline__ float ftanh(float z) {
    float a = fabsf(z);
    float e = __expf(-2.f * a);
    float T = __fdividef(1.f - e, 1.f + e);
    return copysignf(T, z);
}

// jet chain rule for one column given staged pre-activation jet zs[8]
__device__ __forceinline__ void jet7(const float zs[8], float b, float o[7]) {
    float T = ftanh(zs[0] + b);
    float Sx = 1.f - T * T;
    float c2 = -2.f * T * Sx;
    o[0] = T; o[1] = Sx * zs[1]; o[2] = Sx * zs[2]; o[3] = Sx * zs[3];
    o[4] = fmaf(c2 * zs[1], zs[1], Sx * zs[4]);
    o[5] = fmaf(c2 * zs[1], zs[2], Sx * zs[5]);
    o[6] = fmaf(c2 * zs[2], zs[2], Sx * zs[6]);
}

// packed write of cols (c, c+1), c even, one row: bf16x2 hi + bf16x2 lo
__device__ __forceinline__ void writeA_pack(char* smem, int row, int c,
                                            float v0, float v1) {
    uint32_t off = (uint32_t)row * 256u
                 + ((((uint32_t)(c >> 3) ^ ((uint32_t)row & 15u)) << 4)
                 + (((uint32_t)c & 7u) << 1));
    uint32_t hi;
    asm("cvt.rn.satfinite.bf16x2.f32 %0, %1, %2;" : "=r"(hi) : "f"(v1), "f"(v0));
    float l0 = v0 - __uint_as_float(hi << 16);
    float l1 = v1 - __uint_as_float(hi & 0xffff0000u);
    uint32_t lo;
    asm("cvt.rn.satfinite.bf16x2.f32 %0, %1, %2;" : "=r"(lo) : "f"(l1), "f"(l0));
    *(uint32_t*)(smem + SM_AHI + off) = hi;
    *(uint32_t*)(smem + SM_ALO + off) = lo;
}

// per-half 64x128x128 bf16 3-term split GEMM (warp: 16 rows x 64 cols)
__device__ __forceinline__ void gemm_layer(uint32_t su, int ro, int rb, int cg,
                                           int lane, uint32_t whi_off,
                                           float acc[4][2][4]) {
#pragma unroll
    for (int nb = 0; nb < 4; nb++)
#pragma unroll
        for (int h = 0; h < 2; h++)
#pragma unroll
            for (int e = 0; e < 4; e++) acc[nb][h][e] = 0.f;

    const int m = lane >> 3;
    const int row_a = ro + rb * 16 + (lane & 7) + ((m & 1) << 3);
    const int krow_l = (lane & 7) + ((m & 1) << 3);
#pragma unroll
    for (int k = 0; k < 8; k++) {
        uint32_t ua = (uint32_t)((k * 2 + (m >> 1)) ^ (row_a & 15));
        uint32_t aaddr = su + SM_AHI + (uint32_t)row_a * 256u + ua * 16u;
        uint32_t ahi[4], alo[4];
        ldsm4(ahi, aaddr);
        ldsm4(alo, aaddr + 32768u);
#pragma unroll
        for (int nb = 0; nb < 4; nb++) {
            int ncol = cg * 64 + nb * 16;
            int krow = k * 16 + krow_l;
            uint32_t un = (uint32_t)((((ncol >> 3) + (m >> 1))) ^ (krow & 15));
            uint32_t baddr = su + whi_off + (uint32_t)krow * 256u + un * 16u;
            uint32_t bhi[4], blo[4];
            ldsm4t(bhi, baddr);
            ldsm4t(blo, baddr + 32768u);
#pragma unroll
            for (int h = 0; h < 2; h++) {
                mma16816(acc[nb][h], ahi, bhi[2 * h], bhi[2 * h + 1]);
                mma16816(acc[nb][h], ahi, blo[2 * h], blo[2 * h + 1]);
                mma16816(acc[nb][h], alo, bhi[2 * h], bhi[2 * h + 1]);
            }
        }
    }
}

// stage all fragments into the dead A region (full 128 cols at once)
__device__ __forceinline__ void stage_frags(char* smem, int half, int rb, int cg,
                                            int lane, float acc[4][2][4]) {
    const int g = lane >> 2, tg = lane & 3;
    const int rbase = (cg ? SM_ALO : SM_AHI) + half * 16384;
#pragma unroll
    for (int nb = 0; nb < 4; nb++)
#pragma unroll
        for (int h = 0; h < 2; h++)
#pragma unroll
            for (int e = 0; e < 4; e++) {
                int pt = 2 * rb + (e >> 1);
                int col = cg * 64 + nb * 16 + h * 8 + 2 * tg + (e & 1);
                int slotp = (8 * pt + g) ^ ((col & 7) << 2)
                          ^ (((col >> 3) & 1) << 2);
                *(float*)(smem + rbase + (((col & 63) << 6) + slotp) * 4)
                    = acc[nb][h][e];
            }
}

// read staged jet for (point p, column col) -> zs[0..7]
__device__ __forceinline__ void read_stage_col(char* smem, int half, int p,
                                               int col, float zs[8]) {
    char* rbase = smem + ((col >= 64) ? SM_ALO : SM_AHI) + half * 16384
                + (col & 63) * 256;
    int base = (8 * p) ^ ((col & 6) << 2);
    int xb2 = ((col & 1) ^ ((col >> 3) & 1)) << 2;
    float4 f0 = *(float4*)(rbase + (base + xb2) * 4);        // ch 0..3
    float4 f1 = *(float4*)(rbase + (base + (xb2 ^ 4)) * 4);  // ch 4..7
    zs[0] = f0.x; zs[1] = f0.y; zs[2] = f0.z; zs[3] = f0.w;
    zs[4] = f1.x; zs[5] = f1.y; zs[6] = f1.z; zs[7] = f1.w;
}

__global__ __launch_bounds__(NTHREADS, 1)
void pinn_kernel(const float* __restrict__ x,  const float* __restrict__ t,
                 const float* __restrict__ W0, const float* __restrict__ b0,
                 const float* __restrict__ W1, const float* __restrict__ b1,
                 const float* __restrict__ W2, const float* __restrict__ b2,
                 const float* __restrict__ W3, const float* __restrict__ b3,
                 float* __restrict__ out)
{
    extern __shared__ char smem[];
    const uint32_t su = smem_u32_of(smem);
    const int tid = threadIdx.x, warp = tid >> 5, lane = tid & 31;
    const int half = warp >> 3, wid8 = warp & 7;
    const int rb = wid8 & 3, cg = wid8 >> 2;
    const int ro = half * 64;
    const int tid_h = tid & 255;
    const int p_epi = tid_h >> 5, l_epi = tid_h & 31;

    // ---- init: weights (k-major, bf16 hi/lo, swizzled), vectors ----
    for (int idx = tid; idx < 16384; idx += NTHREADS) {
        int k = idx >> 7, n = idx & 127;
        uint32_t off = (uint32_t)k * 256u
                     + ((((uint32_t)(n >> 3) ^ ((uint32_t)k & 15u)) << 4)
                     | (((uint32_t)n & 7u) << 1));
        float w = W1[idx];
        __nv_bfloat16 h = __float2bfloat16(w);
        *(__nv_bfloat16*)(smem + SM_W1HI + off) = h;
        *(__nv_bfloat16*)(smem + SM_W1LO + off) = __float2bfloat16(w - __bfloat162float(h));
        w = W2[idx];
        h = __float2bfloat16(w);
        *(__nv_bfloat16*)(smem + SM_W2HI + off) = h;
        *(__nv_bfloat16*)(smem + SM_W2LO + off) = __float2bfloat16(w - __bfloat162float(h));
    }
    for (int j = tid; j < 128; j += NTHREADS) {
        ((float4*)(smem + SM_W0P))[j] = make_float4(W0[j], W0[128 + j], W0[256 + j], b0[j]);
        ((float4*)(smem + SM_W3P))[j] = make_float4(W3[3 * j], W3[3 * j + 1], W3[3 * j + 2], 0.f);
        ((float*)(smem + SM_B1))[j] = b1[j];
        ((float*)(smem + SM_B2))[j] = b2[j];
    }
    __syncthreads();

    const int t0 = (blockIdx.x * TILES) / NBLOCKS;
    const int t1 = ((blockIdx.x + 1) * TILES) / NBLOCKS;
    double a0 = 0.0, a1 = 0.0, a2 = 0.0;
    const float b3v = b3[0];
    float acc[4][2][4];

    for (int tile = t0; tile < t1; tile++) {
        // ---- layer-0 analytic jet seed -> A (pair-packed; ch7 skipped) ----
        {
            const int pr = tid_h & 63;
            const int c = 2 * pr;
            const float4 wA = ((const float4*)(smem + SM_W0P))[c];
            const float4 wB = ((const float4*)(smem + SM_W0P))[c + 1];
#pragma unroll
            for (int it = 0; it < 2; it++) {
                int p = (tid_h >> 6) + 4 * it;
                int gp = tile * 16 + half * 8 + p;
                float x1 = x[2 * gp], x2 = x[2 * gp + 1], ttv = t[gp];
                float zA = fmaf(ttv, wA.z, fmaf(x2, wA.y, fmaf(x1, wA.x, wA.w)));
                float zB = fmaf(ttv, wB.z, fmaf(x2, wB.y, fmaf(x1, wB.x, wB.w)));
                float TA = ftanh(zA), TB = ftanh(zB);
                float SA = 1.f - TA * TA, SB = 1.f - TB * TB;
                float cA = -2.f * TA * SA, cB = -2.f * TB * SB;
                float oA[7] = {TA, SA * wA.x, SA * wA.y, SA * wA.z,
                               cA * wA.x * wA.x, cA * wA.x * wA.y, cA * wA.y * wA.y};
                float oB[7] = {TB, SB * wB.x, SB * wB.y, SB * wB.z,
                               cB * wB.x * wB.x, cB * wB.x * wB.y, cB * wB.y * wB.y};
#pragma unroll
                for (int ch = 0; ch < 7; ch++)
                    writeA_pack(smem, ro + p * 8 + ch, c, oA[ch], oB[ch]);
            }
        }
        barh(half);

        // ---- hidden layer 1 ----
        gemm_layer(su, ro, rb, cg, lane, SM_W1HI, acc);
        barh(half);                         // all warps done reading A
        stage_frags(smem, half, rb, cg, lane, acc);
        barh(half);                         // stage (in dead A) ready
        {
            float zsA[2][8], zsB[2][8];
#pragma unroll
            for (int qp = 0; qp < 2; qp++) {
                int c = 2 * l_epi + 64 * qp;
                read_stage_col(smem, half, p_epi, c, zsA[qp]);
                read_stage_col(smem, half, p_epi, c + 1, zsB[qp]);
            }
            barh(half);                     // reads in regs; A region free
            const float* B1p = (const float*)(smem + SM_B1);
#pragma unroll
            for (int qp = 0; qp < 2; qp++) {
                int c = 2 * l_epi + 64 * qp;
                float o0[7], o1[7];
                jet7(zsA[qp], B1p[c], o0);
                jet7(zsB[qp], B1p[c + 1], o1);
#pragma unroll
                for (int ch = 0; ch < 7; ch++)
                    writeA_pack(smem, ro + p_epi * 8 + ch, c, o0[ch], o1[ch]);
            }
        }
        barh(half);                         // new A ready

        // ---- hidden layer 2 ----
        gemm_layer(su, ro, rb, cg, lane, SM_W2HI, acc);
        barh(half);
        stage_frags(smem, half, rb, cg, lane, acc);
        barh(half);
        float Jacc[21];
#pragma unroll
        for (int c = 0; c < 21; c++) Jacc[c] = 0.f;
        {
            const float* B2p = (const float*)(smem + SM_B2);
            const float4* W3P = (const float4*)(smem + SM_W3P);
#pragma unroll
            for (int qp = 0; qp < 4; qp++) {
                int c = 2 * l_epi + ((qp & 1)) + 64 * (qp >> 1);
                float zs[8], o[7];
                read_stage_col(smem, half, p_epi, c, zs);
                jet7(zs, B2p[c], o);
                float4 w3 = W3P[c];
#pragma unroll
                for (int ch = 0; ch < 7; ch++) {
                    Jacc[ch * 3 + 0] = fmaf(o[ch], w3.x, Jacc[ch * 3 + 0]);
                    Jacc[ch * 3 + 1] = fmaf(o[ch], w3.y, Jacc[ch * 3 + 1]);
                    Jacc[ch * 3 + 2] = fmaf(o[ch], w3.z, Jacc[ch * 3 + 2]);
                }
            }
        }
        // warp-reduce J over 32 lanes (warp p_epi = one point)
#pragma unroll
        for (int c = 0; c < 21; c++) {
#pragma unroll
            for (int off = 16; off; off >>= 1)
                Jacc[c] += __shfl_down_sync(0xffffffffu, Jacc[c], off);
        }
        if (lane == 0) {
            float* PJ = (float*)(smem + SM_PARTJ) + (half * 8 + wid8) * 24;
#pragma unroll
            for (int c = 0; c < 21; c++) PJ[c] = Jacc[c];
        }
        barh(half);

        // ---- physics residuals (half's warp 0, one lane per point) ----
        if (wid8 == 0 && lane < 8) {
            const float* PJ = (const float*)(smem + SM_PARTJ) + (half * 8 + lane) * 24;
            float J0[7], J1[7], J2[7];
#pragma unroll
            for (int c = 0; c < 7; c++) {
                J0[c] = PJ[c * 3 + 0]; J1[c] = PJ[c * 3 + 1]; J2[c] = PJ[c * 3 + 2];
            }
            float s0v = J0[0] + b3v;
            float phi = expf(-s0v);
            float div1 = (MU + LAM) * (J1[4] + J2[5]) + MU * (J1[4] + J1[6]);
            float div2 = (MU + LAM) * (J1[5] + J2[6]) + MU * (J2[4] + J2[6]);
            float om = 1.f - phi, gq = om * om;
            float res_stress = fabsf(gq * div1) + fabsf(gq * div2);
            float tr = J1[1] + J2[2];
            float trp = 0.5f * (tr + fabsf(tr));
            float pos = 0.5f * (LAM + MU) * trp * trp;
            float e12 = 0.5f * (J1[2] + J2[1]);
            float d11 = J1[1] - 0.5f * tr;
            float d22 = J2[2] - 0.5f * tr;
            float psi = pos + MU * (d11 * d11 + d22 * d22 + 2.f * e12 * e12);
            float lap = phi * (J0[1] * J0[1] + J0[2] * J0[2] - J0[4] - J0[6]);
            float pf = GC * (phi / LEN - LEN * lap) - 2.f * om * psi;
            float irr = fmaxf(phi * J0[3], 0.f);
            a0 += (double)(res_stress * res_stress);
            a1 += (double)(pf * pf);
            a2 += (double)irr;
        }
    }

    // ---- block reduction (deterministic) ----
#pragma unroll
    for (int off = 4; off; off >>= 1) {
        a0 += __shfl_down_sync(0xffffffffu, a0, off);
        a1 += __shfl_down_sync(0xffffffffu, a1, off);
        a2 += __shfl_down_sync(0xffffffffu, a2, off);
    }
    {
        double* wred = (double*)(smem + SM_WRED);
        __syncthreads();
        if (lane == 0) {
            wred[warp * 3 + 0] = a0;
            wred[warp * 3 + 1] = a1;
            wred[warp * 3 + 2] = a2;
        }
        __syncthreads();
        if (tid == 0) {
            double s0 = 0.0, s1 = 0.0, s2 = 0.0;
#pragma unroll
            for (int w = 0; w < 16; w++) {
                s0 += wred[w * 3 + 0]; s1 += wred[w * 3 + 1]; s2 += wred[w * 3 + 2];
            }
            g_part[blockIdx.x][0] = s0;
            g_part[blockIdx.x][1] = s1;
            g_part[blockIdx.x][2] = s2;
        }
    }

    __shared__ int is_last;
    __syncthreads();
    if (tid == 0) {
        __threadfence();
        is_last = (atomicAdd(&g_count, 1) == NBLOCKS - 1) ? 1 : 0;
    }
    __syncthreads();
    if (is_last && warp == 0) {
        __threadfence();
        double s0 = 0.0, s1 = 0.0, s2 = 0.0;
        for (int i = lane; i < NBLOCKS; i += 32) {
            s0 += g_part[i][0]; s1 += g_part[i][1]; s2 += g_part[i][2];
        }
#pragma unroll
        for (int off = 16; off; off >>= 1) {
            s0 += __shfl_down_sync(0xffffffffu, s0, off);
            s1 += __shfl_down_sync(0xffffffffu, s1, off);
            s2 += __shfl_down_sync(0xffffffffu, s2, off);
        }
        if (lane == 0) {
            out[0] = (float)(s0 / (double)NPTS);
            out[1] = (float)(s1 / (double)NPTS);
            out[2] = (float)(s2 / (double)NPTS);
            g_count = 0;
        }
    }
}

extern "C" void kernel_launch(void* const* d_in, const int* in_sizes, int n_in,
                              void* d_out, int out_size)
{
    const float* x  = (const float*)d_in[0];
    const float* t  = (const float*)d_in[1];
    const float* W0 = (const float*)d_in[2];
    const float* b0 = (const float*)d_in[3];
    const float* W1 = (const float*)d_in[4];
    const float* b1 = (const float*)d_in[5];
    const float* W2 = (const float*)d_in[6];
    const float* b2 = (const float*)d_in[7];
    const float* W3 = (const float*)d_in[8];
    const float* b3 = (const float*)d_in[9];

    cudaFuncSetAttribute(pinn_kernel,
                         cudaFuncAttributeMaxDynamicSharedMemorySize, SMEM_TOTAL);
    pinn_kernel<<<NBLOCKS, NTHREADS, SMEM_TOTAL>>>(
        x, t, W0, b0, W1, b1, W2, b2, W3, b3, (float*)d_out);
}

// round 16
// speedup vs baseline: 1.6815x; 1.0375x over previous
#include <cuda_runtime.h>
#include <cuda_bf16.h>
#include <stdint.h>
#include <math.h>

#define NPTS 8192
#define NBLOCKS 148
#define NTHREADS 512
#define TILES 512

#define MU 80.77f
#define LAM 121.15f
#define GC 2.7e-3f
#define LEN 0.015f

// ---- SMEM byte offsets ----
#define SM_AHI   0        // A hi: 128 rows x 256B (bf16, swizzled); quarter q rows q*32..
#define SM_ALO   32768    // A lo
#define SM_W1HI  65536    // W k-major [k][n] bf16, swizzled
#define SM_W1LO  98304
#define SM_W2HI  131072
#define SM_W2LO  163840
#define SM_W0P   196608   // float4[128]: (W0r0, W0r1, W0r2, b0)
#define SM_W3P   198656   // float4[128]: (W3[j][0..2], 0)
#define SM_B1    200704
#define SM_B2    201216
#define SM_WRED  201728   // double[16][3]
#define SMEM_TOTAL 202240

// Stage (z matrix) aliases quarter q's dead A slabs (8KB hi + 8KB lo):
//   col<64 -> hi slab, col>=64 -> lo slab; [col&63] pitch 128B,
//   slot = (8*pt + ch) ^ ((col&7)<<2) ^ (((col>>3)&1)<<2)
//   (conflict-free for fragment stores AND per-point paired reads).

__device__ double g_part[NBLOCKS][3];
__device__ int g_count = 0;

__device__ __forceinline__ uint32_t smem_u32_of(const void* p) {
    uint32_t a;
    asm("{ .reg .u64 tmp; cvta.to.shared.u64 tmp, %1; cvt.u32.u64 %0, tmp; }"
        : "=r"(a) : "l"(p));
    return a;
}
__device__ __forceinline__ void barq(int q) {
    asm volatile("bar.sync %0, 128;" :: "r"(q + 1) : "memory");
}
__device__ __forceinline__ void ldsm4(uint32_t r[4], uint32_t addr) {
    asm volatile("ldmatrix.sync.aligned.m8n8.x4.shared.b16 {%0,%1,%2,%3}, [%4];"
                 : "=r"(r[0]), "=r"(r[1]), "=r"(r[2]), "=r"(r[3]) : "r"(addr));
}
__device__ __forceinline__ void ldsm4t(uint32_t r[4], uint32_t addr) {
    asm volatile("ldmatrix.sync.aligned.m8n8.x4.trans.shared.b16 {%0,%1,%2,%3}, [%4];"
                 : "=r"(r[0]), "=r"(r[1]), "=r"(r[2]), "=r"(r[3]) : "r"(addr));
}
__device__ __forceinline__ void mma16816(float c[4], const uint32_t a[4],
                                         uint32_t b0, uint32_t b1) {
    asm volatile(
        "mma.sync.aligned.m16n8k16.row.col.f32.bf16.bf16.f32 "
        "{%0,%1,%2,%3}, {%4,%5,%6,%7}, {%8,%9}, {%0,%1,%2,%3};"
        : "+f"(c[0]), "+f"(c[1]), "+f"(c[2]), "+f"(c[3])
        : "r"(a[0]), "r"(a[1]), "r"(a[2]), "r"(a[3]), "r"(b0), "r"(b1));
}

// fast tanh: abs error ~1e-7 (MUFU ex2 + approx div)
__device__ __forceinline__ float ftanh(float z) {
    float a = fabsf(z);
    float e = __expf(-2.f * a);
    float T = __fdividef(1.f - e, 1.f + e);
    return copysignf(T, z);
}

// jet chain rule for one column given staged pre-activation jet zs[8]
__device__ __forceinline__ void jet7(const float zs[8], float b, float o[7]) {
    float T = ftanh(zs[0] + b);
    float Sx = 1.f - T * T;
    float c2 = -2.f * T * Sx;
    o[0] = T; o[1] = Sx * zs[1]; o[2] = Sx * zs[2]; o[3] = Sx * zs[3];
    o[4] = fmaf(c2 * zs[1], zs[1], Sx * zs[4]);
    o[5] = fmaf(c2 * zs[1], zs[2], Sx * zs[5]);
    o[6] = fmaf(c2 * zs[2], zs[2], Sx * zs[6]);
}

// packed write of cols (c, c+1), c even, one row: bf16x2 hi + bf16x2 lo
__device__ __forceinline__ void writeA_pack(char* smem, int row, int c,
                                            float v0, float v1) {
    uint32_t off = (uint32_t)row * 256u
                 + ((((uint32_t)(c >> 3) ^ ((uint32_t)row & 15u)) << 4)
                 + (((uint32_t)c & 7u) << 1));
    uint32_t hi;
    asm("cvt.rn.satfinite.bf16x2.f32 %0, %1, %2;" : "=r"(hi) : "f"(v1), "f"(v0));
    float l0 = v0 - __uint_as_float(hi << 16);
    float l1 = v1 - __uint_as_float(hi & 0xffff0000u);
    uint32_t lo;
    asm("cvt.rn.satfinite.bf16x2.f32 %0, %1, %2;" : "=r"(lo) : "f"(l1), "f"(l0));
    *(uint32_t*)(smem + SM_AHI + off) = hi;
    *(uint32_t*)(smem + SM_ALO + off) = lo;
}

// per-quarter 32x128x128 bf16 3-term split GEMM (warp: 16 rows x 64 cols)
__device__ __forceinline__ void gemm_layer(uint32_t su, int ro, int rb, int cg,
                                           int lane, uint32_t whi_off,
                                           float acc[4][2][4]) {
#pragma unroll
    for (int nb = 0; nb < 4; nb++)
#pragma unroll
        for (int h = 0; h < 2; h++)
#pragma unroll
            for (int e = 0; e < 4; e++) acc[nb][h][e] = 0.f;

    const int m = lane >> 3;
    const int row_a = ro + rb * 16 + (lane & 7) + ((m & 1) << 3);
    const int krow_l = (lane & 7) + ((m & 1) << 3);
#pragma unroll
    for (int k = 0; k < 8; k++) {
        uint32_t ua = (uint32_t)((k * 2 + (m >> 1)) ^ (row_a & 15));
        uint32_t aaddr = su + SM_AHI + (uint32_t)row_a * 256u + ua * 16u;
        uint32_t ahi[4], alo[4];
        ldsm4(ahi, aaddr);
        ldsm4(alo, aaddr + 32768u);
#pragma unroll
        for (int nb = 0; nb < 4; nb++) {
            int ncol = cg * 64 + nb * 16;
            int krow = k * 16 + krow_l;
            uint32_t un = (uint32_t)((((ncol >> 3) + (m >> 1))) ^ (krow & 15));
            uint32_t baddr = su + whi_off + (uint32_t)krow * 256u + un * 16u;
            uint32_t bhi[4], blo[4];
            ldsm4t(bhi, baddr);
            ldsm4t(blo, baddr + 32768u);
#pragma unroll
            for (int h = 0; h < 2; h++) {
                mma16816(acc[nb][h], ahi, bhi[2 * h], bhi[2 * h + 1]);
                mma16816(acc[nb][h], ahi, blo[2 * h], blo[2 * h + 1]);
                mma16816(acc[nb][h], alo, bhi[2 * h], bhi[2 * h + 1]);
            }
        }
    }
}

// stage all fragments into the quarter's dead A slabs
__device__ __forceinline__ void stage_frags(char* smem, int q, int rb, int cg,
                                            int lane, float acc[4][2][4]) {
    const int g = lane >> 2, tg = lane & 3;
    const int rbase = (cg ? SM_ALO : SM_AHI) + q * 8192;
#pragma unroll
    for (int nb = 0; nb < 4; nb++)
#pragma unroll
        for (int h = 0; h < 2; h++)
#pragma unroll
            for (int e = 0; e < 4; e++) {
                int pt = 2 * rb + (e >> 1);
                int col = cg * 64 + nb * 16 + h * 8 + 2 * tg + (e & 1);
                int slot = (8 * pt + g) ^ ((col & 7) << 2)
                         ^ (((col >> 3) & 1) << 2);
                *(float*)(smem + rbase + ((col & 63) << 7) + slot * 4)
                    = acc[nb][h][e];
            }
}

// read staged jet for (quarter-local point pt, column col) -> zs[0..7]
__device__ __forceinline__ void read_stage_col(char* smem, int q, int pt,
                                               int col, float zs[8]) {
    char* rbase = smem + ((col >= 64) ? SM_ALO : SM_AHI) + q * 8192
                + ((col & 63) << 7);
    int X = ((col & 7) << 2) ^ (((col >> 3) & 1) << 2);
    int s0 = (8 * pt) ^ X;
    float4 f0 = *(float4*)(rbase + s0 * 4);        // ch 0..3
    float4 f1 = *(float4*)(rbase + (s0 ^ 4) * 4);  // ch 4..7
    zs[0] = f0.x; zs[1] = f0.y; zs[2] = f0.z; zs[3] = f0.w;
    zs[4] = f1.x; zs[5] = f1.y; zs[6] = f1.z; zs[7] = f1.w;
}

__global__ __launch_bounds__(NTHREADS, 1)
void pinn_kernel(const float* __restrict__ x,  const float* __restrict__ t,
                 const float* __restrict__ W0, const float* __restrict__ b0,
                 const float* __restrict__ W1, const float* __restrict__ b1,
                 const float* __restrict__ W2, const float* __restrict__ b2,
                 const float* __restrict__ W3, const float* __restrict__ b3,
                 float* __restrict__ out)
{
    extern __shared__ char smem[];
    const uint32_t su = smem_u32_of(smem);
    const int tid = threadIdx.x, warp = tid >> 5, lane = tid & 31;
    const int q = warp >> 2, lw = warp & 3;        // quarter, warp-in-quarter
    const int rb = lw & 1, cg = lw >> 1;
    const int ro = q * 32;
    const int tid_q = tid & 127;

    // ---- init: weights (k-major, bf16 hi/lo, swizzled), vectors ----
    for (int idx = tid; idx < 16384; idx += NTHREADS) {
        int k = idx >> 7, n = idx & 127;
        uint32_t off = (uint32_t)k * 256u
                     + ((((uint32_t)(n >> 3) ^ ((uint32_t)k & 15u)) << 4)
                     | (((uint32_t)n & 7u) << 1));
        float w = W1[idx];
        __nv_bfloat16 h = __float2bfloat16(w);
        *(__nv_bfloat16*)(smem + SM_W1HI + off) = h;
        *(__nv_bfloat16*)(smem + SM_W1LO + off) = __float2bfloat16(w - __bfloat162float(h));
        w = W2[idx];
        h = __float2bfloat16(w);
        *(__nv_bfloat16*)(smem + SM_W2HI + off) = h;
        *(__nv_bfloat16*)(smem + SM_W2LO + off) = __float2bfloat16(w - __bfloat162float(h));
    }
    for (int j = tid; j < 128; j += NTHREADS) {
        ((float4*)(smem + SM_W0P))[j] = make_float4(W0[j], W0[128 + j], W0[256 + j], b0[j]);
        ((float4*)(smem + SM_W3P))[j] = make_float4(W3[3 * j], W3[3 * j + 1], W3[3 * j + 2], 0.f);
        ((float*)(smem + SM_B1))[j] = b1[j];
        ((float*)(smem + SM_B2))[j] = b2[j];
    }
    __syncthreads();

    const int t0 = (blockIdx.x * TILES) / NBLOCKS;
    const int t1 = ((blockIdx.x + 1) * TILES) / NBLOCKS;
    double a0 = 0.0, a1 = 0.0, a2 = 0.0;
    const float b3v = b3[0];
    float acc[4][2][4];

    for (int tile = t0; tile < t1; tile++) {
        // ---- layer-0 analytic jet seed -> quarter's A rows (pair-packed) ----
        {
            const int pr = tid_q & 63;
            const int c = 2 * pr;
            const float4 wA = ((const float4*)(smem + SM_W0P))[c];
            const float4 wB = ((const float4*)(smem + SM_W0P))[c + 1];
#pragma unroll
            for (int it = 0; it < 2; it++) {
                int p = (tid_q >> 6) + 2 * it;         // 0..3 within quarter
                int gp = tile * 16 + q * 4 + p;
                float x1 = x[2 * gp], x2 = x[2 * gp + 1], ttv = t[gp];
                float zA = fmaf(ttv, wA.z, fmaf(x2, wA.y, fmaf(x1, wA.x, wA.w)));
                float zB = fmaf(ttv, wB.z, fmaf(x2, wB.y, fmaf(x1, wB.x, wB.w)));
                float TA = ftanh(zA), TB = ftanh(zB);
                float SA = 1.f - TA * TA, SB = 1.f - TB * TB;
                float cA = -2.f * TA * SA, cB = -2.f * TB * SB;
                float oA[7] = {TA, SA * wA.x, SA * wA.y, SA * wA.z,
                               cA * wA.x * wA.x, cA * wA.x * wA.y, cA * wA.y * wA.y};
                float oB[7] = {TB, SB * wB.x, SB * wB.y, SB * wB.z,
                               cB * wB.x * wB.x, cB * wB.x * wB.y, cB * wB.y * wB.y};
#pragma unroll
                for (int ch = 0; ch < 7; ch++)
                    writeA_pack(smem, ro + p * 8 + ch, c, oA[ch], oB[ch]);
            }
        }
        barq(q);

        // ---- hidden layer 1 ----
        gemm_layer(su, ro, rb, cg, lane, SM_W1HI, acc);
        barq(q);                            // all quarter warps done reading A
        stage_frags(smem, q, rb, cg, lane, acc);
        barq(q);                            // stage (in dead A) ready
        {
            float zsA[2][8], zsB[2][8];
#pragma unroll
            for (int qp = 0; qp < 2; qp++) {
                int c = 2 * lane + 64 * qp;
                read_stage_col(smem, q, lw, c, zsA[qp]);
                read_stage_col(smem, q, lw, c + 1, zsB[qp]);
            }
            barq(q);                        // reads in regs; A region free
            const float* B1p = (const float*)(smem + SM_B1);
#pragma unroll
            for (int qp = 0; qp < 2; qp++) {
                int c = 2 * lane + 64 * qp;
                float o0[7], o1[7];
                jet7(zsA[qp], B1p[c], o0);
                jet7(zsB[qp], B1p[c + 1], o1);
#pragma unroll
                for (int ch = 0; ch < 7; ch++)
                    writeA_pack(smem, ro + lw * 8 + ch, c, o0[ch], o1[ch]);
            }
        }
        barq(q);                            // new A ready

        // ---- hidden layer 2 ----
        gemm_layer(su, ro, rb, cg, lane, SM_W2HI, acc);
        barq(q);
        stage_frags(smem, q, rb, cg, lane, acc);
        barq(q);
        float Jacc[21];
#pragma unroll
        for (int c = 0; c < 21; c++) Jacc[c] = 0.f;
        {
            const float* B2p = (const float*)(smem + SM_B2);
            const float4* W3P = (const float4*)(smem + SM_W3P);
#pragma unroll
            for (int qp = 0; qp < 4; qp++) {
                int c = 2 * lane + (qp & 1) + 64 * (qp >> 1);
                float zs[8], o[7];
                read_stage_col(smem, q, lw, c, zs);
                jet7(zs, B2p[c], o);
                float4 w3 = W3P[c];
#pragma unroll
                for (int ch = 0; ch < 7; ch++) {
                    Jacc[ch * 3 + 0] = fmaf(o[ch], w3.x, Jacc[ch * 3 + 0]);
                    Jacc[ch * 3 + 1] = fmaf(o[ch], w3.y, Jacc[ch * 3 + 1]);
                    Jacc[ch * 3 + 2] = fmaf(o[ch], w3.z, Jacc[ch * 3 + 2]);
                }
            }
        }
        barq(q);                            // stage reads done; A free for next seed

        // warp-reduce J: this warp covers ALL 128 cols of its point
#pragma unroll
        for (int c = 0; c < 21; c++) {
#pragma unroll
            for (int off = 16; off; off >>= 1)
                Jacc[c] += __shfl_down_sync(0xffffffffu, Jacc[c], off);
        }

        // ---- physics residuals: lane 0 of each warp owns one point ----
        if (lane == 0) {
            float J0[7], J1[7], J2[7];
#pragma unroll
            for (int c = 0; c < 7; c++) {
                J0[c] = Jacc[c * 3 + 0]; J1[c] = Jacc[c * 3 + 1]; J2[c] = Jacc[c * 3 + 2];
            }
            float s0v = J0[0] + b3v;
            float phi = expf(-s0v);
            float div1 = (MU + LAM) * (J1[4] + J2[5]) + MU * (J1[4] + J1[6]);
            float div2 = (MU + LAM) * (J1[5] + J2[6]) + MU * (J2[4] + J2[6]);
            float om = 1.f - phi, gq = om * om;
            float res_stress = fabsf(gq * div1) + fabsf(gq * div2);
            float tr = J1[1] + J2[2];
            float trp = 0.5f * (tr + fabsf(tr));
            float pos = 0.5f * (LAM + MU) * trp * trp;
            float e12 = 0.5f * (J1[2] + J2[1]);
            float d11 = J1[1] - 0.5f * tr;
            float d22 = J2[2] - 0.5f * tr;
            float psi = pos + MU * (d11 * d11 + d22 * d22 + 2.f * e12 * e12);
            float lap = phi * (J0[1] * J0[1] + J0[2] * J0[2] - J0[4] - J0[6]);
            float pf = GC * (phi / LEN - LEN * lap) - 2.f * om * psi;
            float irr = fmaxf(phi * J0[3], 0.f);
            a0 += (double)(res_stress * res_stress);
            a1 += (double)(pf * pf);
            a2 += (double)irr;
        }
    }

    // ---- block reduction (deterministic; data only in lane 0 of each warp) ----
#pragma unroll
    for (int off = 16; off; off >>= 1) {
        a0 += __shfl_down_sync(0xffffffffu, a0, off);
        a1 += __shfl_down_sync(0xffffffffu, a1, off);
        a2 += __shfl_down_sync(0xffffffffu, a2, off);
    }
    {
        double* wred = (double*)(smem + SM_WRED);
        __syncthreads();
        if (lane == 0) {
            wred[warp * 3 + 0] = a0;
            wred[warp * 3 + 1] = a1;
            wred[warp * 3 + 2] = a2;
        }
        __syncthreads();
        if (tid == 0) {
            double s0 = 0.0, s1 = 0.0, s2 = 0.0;
#pragma unroll
            for (int w = 0; w < 16; w++) {
                s0 += wred[w * 3 + 0]; s1 += wred[w * 3 + 1]; s2 += wred[w * 3 + 2];
            }
            g_part[blockIdx.x][0] = s0;
            g_part[blockIdx.x][1] = s1;
            g_part[blockIdx.x][2] = s2;
        }
    }

    __shared__ int is_last;
    __syncthreads();
    if (tid == 0) {
        __threadfence();
        is_last = (atomicAdd(&g_count, 1) == NBLOCKS - 1) ? 1 : 0;
    }
    __syncthreads();
    if (is_last && warp == 0) {
        __threadfence();
        double s0 = 0.0, s1 = 0.0, s2 = 0.0;
        for (int i = lane; i < NBLOCKS; i += 32) {
            s0 += g_part[i][0]; s1 += g_part[i][1]; s2 += g_part[i][2];
        }
#pragma unroll
        for (int off = 16; off; off >>= 1) {
            s0 += __shfl_down_sync(0xffffffffu, s0, off);
            s1 += __shfl_down_sync(0xffffffffu, s1, off);
            s2 += __shfl_down_sync(0xffffffffu, s2, off);
        }
        if (lane == 0) {
            out[0] = (float)(s0 / (double)NPTS);
            out[1] = (float)(s1 / (double)NPTS);
            out[2] = (float)(s2 / (double)NPTS);
            g_count = 0;
        }
    }
}

extern "C" void kernel_launch(void* const* d_in, const int* in_sizes, int n_in,
                              void* d_out, int out_size)
{
    const float* x  = (const float*)d_in[0];
    const float* t  = (const float*)d_in[1];
    const float* W0 = (const float*)d_in[2];
    const float* b0 = (const float*)d_in[3];
    const float* W1 = (const float*)d_in[4];
    const float* b1 = (const float*)d_in[5];
    const float* W2 = (const float*)d_in[6];
    const float* b2 = (const float*)d_in[7];
    const float* W3 = (const float*)d_in[8];
    const float* b3 = (const float*)d_in[9];

    cudaFuncSetAttribute(pinn_kernel,
                         cudaFuncAttributeMaxDynamicSharedMemorySize, SMEM_TOTAL);
    pinn_kernel<<<NBLOCKS, NTHREADS, SMEM_TOTAL>>>(
        x, t, W0, b0, W1, b1, W2, b2, W3, b3, (float*)d_out);
}

// round 17
// speedup vs baseline: 2.0817x; 1.2380x over previous
#include <cuda_runtime.h>
#include <cuda_fp16.h>
#include <stdint.h>
#include <math.h>

#define NPTS 8192
#define NBLOCKS 148
#define NTHREADS 512
#define TILES 512

#define MU 80.77f
#define LAM 121.15f
#define GC 2.7e-3f
#define LEN 0.015f

// ---- SMEM byte offsets ----
#define SM_AHI   0        // A hi: 128 rows x 256B (fp16, swizzled); quarter q rows q*32..
#define SM_ALO   32768    // A lo (fp16 residual)
#define SM_W1    65536    // W1 k-major [k][n] fp16, swizzled (single precision tile)
#define SM_W2    98304
#define SM_STAGE 131072   // dedicated stage: 4 quarters x 16KB ([col]x128B, swizzled slots)
#define SM_W0P   196608   // float4[128]: (W0r0, W0r1, W0r2, b0)
#define SM_W3P   198656   // float4[128]: (W3[j][0..2], 0)
#define SM_B1    200704
#define SM_B2    201216
#define SM_WRED  201728   // double[16][3]
#define SMEM_TOTAL 202240

__device__ double g_part[NBLOCKS][3];
__device__ int g_count = 0;

__device__ __forceinline__ uint32_t smem_u32_of(const void* p) {
    uint32_t a;
    asm("{ .reg .u64 tmp; cvta.to.shared.u64 tmp, %1; cvt.u32.u64 %0, tmp; }"
        : "=r"(a) : "l"(p));
    return a;
}
__device__ __forceinline__ void barq(int q) {
    asm volatile("bar.sync %0, 128;" :: "r"(q + 1) : "memory");
}
__device__ __forceinline__ void ldsm4(uint32_t r[4], uint32_t addr) {
    asm volatile("ldmatrix.sync.aligned.m8n8.x4.shared.b16 {%0,%1,%2,%3}, [%4];"
                 : "=r"(r[0]), "=r"(r[1]), "=r"(r[2]), "=r"(r[3]) : "r"(addr));
}
__device__ __forceinline__ void ldsm4t(uint32_t r[4], uint32_t addr) {
    asm volatile("ldmatrix.sync.aligned.m8n8.x4.trans.shared.b16 {%0,%1,%2,%3}, [%4];"
                 : "=r"(r[0]), "=r"(r[1]), "=r"(r[2]), "=r"(r[3]) : "r"(addr));
}
__device__ __forceinline__ void mma16816(float c[4], const uint32_t a[4],
                                         uint32_t b0, uint32_t b1) {
    asm volatile(
        "mma.sync.aligned.m16n8k16.row.col.f32.f16.f16.f32 "
        "{%0,%1,%2,%3}, {%4,%5,%6,%7}, {%8,%9}, {%0,%1,%2,%3};"
        : "+f"(c[0]), "+f"(c[1]), "+f"(c[2]), "+f"(c[3])
        : "r"(a[0]), "r"(a[1]), "r"(a[2]), "r"(a[3]), "r"(b0), "r"(b1));
}

// fast tanh: abs error ~1e-7 (MUFU ex2 + approx div)
__device__ __forceinline__ float ftanh(float z) {
    float a = fabsf(z);
    float e = __expf(-2.f * a);
    float T = __fdividef(1.f - e, 1.f + e);
    return copysignf(T, z);
}

// jet chain rule for one column given staged pre-activation jet zs[8]
__device__ __forceinline__ void jet7(const float zs[8], float b, float o[7]) {
    float T = ftanh(zs[0] + b);
    float Sx = 1.f - T * T;
    float c2 = -2.f * T * Sx;
    o[0] = T; o[1] = Sx * zs[1]; o[2] = Sx * zs[2]; o[3] = Sx * zs[3];
    o[4] = fmaf(c2 * zs[1], zs[1], Sx * zs[4]);
    o[5] = fmaf(c2 * zs[1], zs[2], Sx * zs[5]);
    o[6] = fmaf(c2 * zs[2], zs[2], Sx * zs[6]);
}

// packed write of cols (c, c+1), c even, one row: fp16x2 hi + fp16x2 lo residual
__device__ __forceinline__ void writeA_pack(char* smem, int row, int c,
                                            float v0, float v1) {
    uint32_t off = (uint32_t)row * 256u
                 + ((((uint32_t)(c >> 3) ^ ((uint32_t)row & 15u)) << 4)
                 + (((uint32_t)c & 7u) << 1));
    __half h0 = __float2half_rn(v0);
    __half h1 = __float2half_rn(v1);
    uint32_t hi = ((uint32_t)__half_as_ushort(h1) << 16) | __half_as_ushort(h0);
    __half l0 = __float2half_rn(v0 - __half2float(h0));
    __half l1 = __float2half_rn(v1 - __half2float(h1));
    uint32_t lo = ((uint32_t)__half_as_ushort(l1) << 16) | __half_as_ushort(l0);
    *(uint32_t*)(smem + SM_AHI + off) = hi;
    *(uint32_t*)(smem + SM_ALO + off) = lo;
}

// per-quarter 32x128x128 fp16 2-term split GEMM (warp: 32 rows x 32 cols)
__device__ __forceinline__ void gemm_layer(uint32_t su, int ro, int lw, int lane,
                                           uint32_t w_off, float acc[2][2][2][4]) {
#pragma unroll
    for (int r = 0; r < 2; r++)
#pragma unroll
        for (int nb = 0; nb < 2; nb++)
#pragma unroll
            for (int h = 0; h < 2; h++)
#pragma unroll
                for (int e = 0; e < 4; e++) acc[r][nb][h][e] = 0.f;

    const int m = lane >> 3;
    const int row16 = (lane & 7) + ((m & 1) << 3);
    const int krow_l = row16;
#pragma unroll
    for (int k = 0; k < 8; k++) {
        uint32_t ahi[2][4], alo[2][4], bhi[2][4];
#pragma unroll
        for (int r = 0; r < 2; r++) {
            int row_a = ro + r * 16 + row16;
            uint32_t ua = (uint32_t)((k * 2 + (m >> 1)) ^ (row_a & 15));
            uint32_t aaddr = su + SM_AHI + (uint32_t)row_a * 256u + ua * 16u;
            ldsm4(ahi[r], aaddr);
            ldsm4(alo[r], aaddr + 32768u);
        }
#pragma unroll
        for (int nb = 0; nb < 2; nb++) {
            int ncol = lw * 32 + nb * 16;
            int krow = k * 16 + krow_l;
            uint32_t un = (uint32_t)((((ncol >> 3) + (m >> 1))) ^ (krow & 15));
            ldsm4t(bhi[nb], su + w_off + (uint32_t)krow * 256u + un * 16u);
        }
#pragma unroll
        for (int r = 0; r < 2; r++)
#pragma unroll
            for (int nb = 0; nb < 2; nb++)
#pragma unroll
                for (int h = 0; h < 2; h++) {
                    mma16816(acc[r][nb][h], ahi[r], bhi[nb][2 * h], bhi[nb][2 * h + 1]);
                    mma16816(acc[r][nb][h], alo[r], bhi[nb][2 * h], bhi[nb][2 * h + 1]);
                }
    }
}

// stage all fragments into the quarter's dedicated stage region
__device__ __forceinline__ void stage_frags(char* smem, int q, int lw,
                                            int lane, float acc[2][2][2][4]) {
    const int g = lane >> 2, tg = lane & 3;
    char* base = smem + SM_STAGE + q * 16384;
#pragma unroll
    for (int r = 0; r < 2; r++)
#pragma unroll
        for (int nb = 0; nb < 2; nb++)
#pragma unroll
            for (int h = 0; h < 2; h++)
#pragma unroll
                for (int e = 0; e < 4; e++) {
                    int pt = 2 * r + (e >> 1);
                    int col = lw * 32 + nb * 16 + h * 8 + 2 * tg + (e & 1);
                    int slot = (8 * pt + g) ^ ((col & 7) << 2)
                             ^ (((col >> 3) & 1) << 2);
                    *(float*)(base + (col << 7) + slot * 4) = acc[r][nb][h][e];
                }
}

// read staged jet for (quarter-local point pt, column col) -> zs[0..7]
__device__ __forceinline__ void read_stage_col(char* smem, int q, int pt,
                                               int col, float zs[8]) {
    char* base = smem + SM_STAGE + q * 16384 + (col << 7);
    int X = ((col & 7) << 2) ^ (((col >> 3) & 1) << 2);
    int s0 = (8 * pt) ^ X;
    float4 f0 = *(float4*)(base + s0 * 4);        // ch 0..3
    float4 f1 = *(float4*)(base + (s0 ^ 4) * 4);  // ch 4..7
    zs[0] = f0.x; zs[1] = f0.y; zs[2] = f0.z; zs[3] = f0.w;
    zs[4] = f1.x; zs[5] = f1.y; zs[6] = f1.z; zs[7] = f1.w;
}

// layer-0 analytic jet seed for this quarter's 4 points of tile `tile`
__device__ __forceinline__ void seed_tile(char* smem, int q, int tid_q, int tile,
                                          const float* __restrict__ x,
                                          const float* __restrict__ t) {
    const int ro = q * 32;
    const int pr = tid_q & 63;
    const int c = 2 * pr;
    const float4 wA = ((const float4*)(smem + SM_W0P))[c];
    const float4 wB = ((const float4*)(smem + SM_W0P))[c + 1];
#pragma unroll
    for (int it = 0; it < 2; it++) {
        int p = (tid_q >> 6) + 2 * it;             // 0..3 within quarter
        int gp = tile * 16 + q * 4 + p;
        float x1 = x[2 * gp], x2 = x[2 * gp + 1], ttv = t[gp];
        float zA = fmaf(ttv, wA.z, fmaf(x2, wA.y, fmaf(x1, wA.x, wA.w)));
        float zB = fmaf(ttv, wB.z, fmaf(x2, wB.y, fmaf(x1, wB.x, wB.w)));
        float TA = ftanh(zA), TB = ftanh(zB);
        float SA = 1.f - TA * TA, SB = 1.f - TB * TB;
        float cA = -2.f * TA * SA, cB = -2.f * TB * SB;
        float oA[7] = {TA, SA * wA.x, SA * wA.y, SA * wA.z,
                       cA * wA.x * wA.x, cA * wA.x * wA.y, cA * wA.y * wA.y};
        float oB[7] = {TB, SB * wB.x, SB * wB.y, SB * wB.z,
                       cB * wB.x * wB.x, cB * wB.x * wB.y, cB * wB.y * wB.y};
#pragma unroll
        for (int ch = 0; ch < 7; ch++)
            writeA_pack(smem, ro + p * 8 + ch, c, oA[ch], oB[ch]);
    }
}

__global__ __launch_bounds__(NTHREADS, 1)
void pinn_kernel(const float* __restrict__ x,  const float* __restrict__ t,
                 const float* __restrict__ W0, const float* __restrict__ b0,
                 const float* __restrict__ W1, const float* __restrict__ b1,
                 const float* __restrict__ W2, const float* __restrict__ b2,
                 const float* __restrict__ W3, const float* __restrict__ b3,
                 float* __restrict__ out)
{
    extern __shared__ char smem[];
    const uint32_t su = smem_u32_of(smem);
    const int tid = threadIdx.x, warp = tid >> 5, lane = tid & 31;
    const int q = warp >> 2, lw = warp & 3;        // quarter, warp-in-quarter
    const int ro = q * 32;
    const int tid_q = tid & 127;

    // ---- init: weights (k-major, fp16, swizzled), vectors ----
    for (int idx = tid; idx < 16384; idx += NTHREADS) {
        int k = idx >> 7, n = idx & 127;
        uint32_t off = (uint32_t)k * 256u
                     + ((((uint32_t)(n >> 3) ^ ((uint32_t)k & 15u)) << 4)
                     | (((uint32_t)n & 7u) << 1));
        *(__half*)(smem + SM_W1 + off) = __float2half_rn(W1[idx]);
        *(__half*)(smem + SM_W2 + off) = __float2half_rn(W2[idx]);
    }
    for (int j = tid; j < 128; j += NTHREADS) {
        ((float4*)(smem + SM_W0P))[j] = make_float4(W0[j], W0[128 + j], W0[256 + j], b0[j]);
        ((float4*)(smem + SM_W3P))[j] = make_float4(W3[3 * j], W3[3 * j + 1], W3[3 * j + 2], 0.f);
        ((float*)(smem + SM_B1))[j] = b1[j];
        ((float*)(smem + SM_B2))[j] = b2[j];
    }
    __syncthreads();

    const int t0 = (blockIdx.x * TILES) / NBLOCKS;
    const int t1 = ((blockIdx.x + 1) * TILES) / NBLOCKS;
    double a0 = 0.0, a1 = 0.0, a2 = 0.0;
    const float b3v = b3[0];
    float acc[2][2][2][4];

    // seed first tile's A
    seed_tile(smem, q, tid_q, t0, x, t);
    barq(q);

    for (int tile = t0; tile < t1; tile++) {
        // ---- hidden layer 1: GEMM + stage, then epilogue writes new A ----
        gemm_layer(su, ro, lw, lane, SM_W1, acc);
        stage_frags(smem, q, lw, lane, acc);
        barq(q);                            // stage ready; all warps done with A
        {
            const float* B1p = (const float*)(smem + SM_B1);
#pragma unroll
            for (int qp = 0; qp < 2; qp++) {
                int c = 2 * lane + 64 * qp;
                float zsA[8], zsB[8], o0[7], o1[7];
                read_stage_col(smem, q, lw, c, zsA);
                read_stage_col(smem, q, lw, c + 1, zsB);
                jet7(zsA, B1p[c], o0);
                jet7(zsB, B1p[c + 1], o1);
#pragma unroll
                for (int ch = 0; ch < 7; ch++)
                    writeA_pack(smem, ro + lw * 8 + ch, c, o0[ch], o1[ch]);
            }
        }
        barq(q);                            // new A ready

        // ---- hidden layer 2: GEMM + stage, epilogue folds W3 (+ next seed) ----
        gemm_layer(su, ro, lw, lane, SM_W2, acc);
        stage_frags(smem, q, lw, lane, acc);
        barq(q);                            // stage ready; A free for next seed
        float Jacc[21];
#pragma unroll
        for (int c = 0; c < 21; c++) Jacc[c] = 0.f;
        {
            const float* B2p = (const float*)(smem + SM_B2);
            const float4* W3P = (const float4*)(smem + SM_W3P);
#pragma unroll
            for (int qp = 0; qp < 4; qp++) {
                int c = 2 * lane + (qp & 1) + 64 * (qp >> 1);
                float zs[8], o[7];
                read_stage_col(smem, q, lw, c, zs);
                jet7(zs, B2p[c], o);
                float4 w3 = W3P[c];
#pragma unroll
                for (int ch = 0; ch < 7; ch++) {
                    Jacc[ch * 3 + 0] = fmaf(o[ch], w3.x, Jacc[ch * 3 + 0]);
                    Jacc[ch * 3 + 1] = fmaf(o[ch], w3.y, Jacc[ch * 3 + 1]);
                    Jacc[ch * 3 + 2] = fmaf(o[ch], w3.z, Jacc[ch * 3 + 2]);
                }
            }
        }
        // overlap: seed next tile's A in the same phase (stage & A disjoint now)
        if (tile + 1 < t1) seed_tile(smem, q, tid_q, tile + 1, x, t);

        // warp-reduce J: this warp covers ALL 128 cols of its point
#pragma unroll
        for (int c = 0; c < 21; c++) {
#pragma unroll
            for (int off = 16; off; off >>= 1)
                Jacc[c] += __shfl_down_sync(0xffffffffu, Jacc[c], off);
        }
        // ---- physics residuals: lane 0 of each warp owns one point ----
        if (lane == 0) {
            float J0[7], J1[7], J2[7];
#pragma unroll
            for (int c = 0; c < 7; c++) {
                J0[c] = Jacc[c * 3 + 0]; J1[c] = Jacc[c * 3 + 1]; J2[c] = Jacc[c * 3 + 2];
            }
            float s0v = J0[0] + b3v;
            float phi = expf(-s0v);
            float div1 = (MU + LAM) * (J1[4] + J2[5]) + MU * (J1[4] + J1[6]);
            float div2 = (MU + LAM) * (J1[5] + J2[6]) + MU * (J2[4] + J2[6]);
            float om = 1.f - phi, gq = om * om;
            float res_stress = fabsf(gq * div1) + fabsf(gq * div2);
            float tr = J1[1] + J2[2];
            float trp = 0.5f * (tr + fabsf(tr));
            float pos = 0.5f * (LAM + MU) * trp * trp;
            float e12 = 0.5f * (J1[2] + J2[1]);
            float d11 = J1[1] - 0.5f * tr;
            float d22 = J2[2] - 0.5f * tr;
            float psi = pos + MU * (d11 * d11 + d22 * d22 + 2.f * e12 * e12);
            float lap = phi * (J0[1] * J0[1] + J0[2] * J0[2] - J0[4] - J0[6]);
            float pf = GC * (phi / LEN - LEN * lap) - 2.f * om * psi;
            float irr = fmaxf(phi * J0[3], 0.f);
            a0 += (double)(res_stress * res_stress);
            a1 += (double)(pf * pf);
            a2 += (double)irr;
        }
        barq(q);                            // seed-A writes visible to next GEMM
    }

    // ---- block reduction (deterministic; data only in lane 0 of each warp) ----
#pragma unroll
    for (int off = 16; off; off >>= 1) {
        a0 += __shfl_down_sync(0xffffffffu, a0, off);
        a1 += __shfl_down_sync(0xffffffffu, a1, off);
        a2 += __shfl_down_sync(0xffffffffu, a2, off);
    }
    {
        double* wred = (double*)(smem + SM_WRED);
        __syncthreads();
        if (lane == 0) {
            wred[warp * 3 + 0] = a0;
            wred[warp * 3 + 1] = a1;
            wred[warp * 3 + 2] = a2;
        }
        __syncthreads();
        if (tid == 0) {
            double s0 = 0.0, s1 = 0.0, s2 = 0.0;
#pragma unroll
            for (int w = 0; w < 16; w++) {
                s0 += wred[w * 3 + 0]; s1 += wred[w * 3 + 1]; s2 += wred[w * 3 + 2];
            }
            g_part[blockIdx.x][0] = s0;
            g_part[blockIdx.x][1] = s1;
            g_part[blockIdx.x][2] = s2;
        }
    }

    __shared__ int is_last;
    __syncthreads();
    if (tid == 0) {
        __threadfence();
        is_last = (atomicAdd(&g_count, 1) == NBLOCKS - 1) ? 1 : 0;
    }
    __syncthreads();
    if (is_last && warp == 0) {
        __threadfence();
        double s0 = 0.0, s1 = 0.0, s2 = 0.0;
        for (int i = lane; i < NBLOCKS; i += 32) {
            s0 += g_part[i][0]; s1 += g_part[i][1]; s2 += g_part[i][2];
        }
#pragma unroll
        for (int off = 16; off; off >>= 1) {
            s0 += __shfl_down_sync(0xffffffffu, s0, off);
            s1 += __shfl_down_sync(0xffffffffu, s1, off);
            s2 += __shfl_down_sync(0xffffffffu, s2, off);
        }
        if (lane == 0) {
            out[0] = (float)(s0 / (double)NPTS);
            out[1] = (float)(s1 / (double)NPTS);
            out[2] = (float)(s2 / (double)NPTS);
            g_count = 0;
        }
    }
}

extern "C" void kernel_launch(void* const* d_in, const int* in_sizes, int n_in,
                              void* d_out, int out_size)
{
    const float* x  = (const float*)d_in[0];
    const float* t  = (const float*)d_in[1];
    const float* W0 = (const float*)d_in[2];
    const float* b0 = (const float*)d_in[3];
    const float* W1 = (const float*)d_in[4];
    const float* b1 = (const float*)d_in[5];
    const float* W2 = (const float*)d_in[6];
    const float* b2 = (const float*)d_in[7];
    const float* W3 = (const float*)d_in[8];
    const float* b3 = (const float*)d_in[9];

    cudaFuncSetAttribute(pinn_kernel,
                         cudaFuncAttributeMaxDynamicSharedMemorySize, SMEM_TOTAL);
    pinn_kernel<<<NBLOCKS, NTHREADS, SMEM_TOTAL>>>(
        x, t, W0, b0, W1, b1, W2, b2, W3, b3, (float*)d_out);
}